// round 3
// baseline (speedup 1.0000x reference)
#include <cuda_runtime.h>
#include <math.h>

#define NN 384
#define DD 512
#define HH 8
#define FF 64

// ---- scratch (no allocations allowed) ----
__device__ float d_gl[NN * DD];
__device__ float d_gr[NN * DD];
__device__ float d_E[HH * NN * NN];
__device__ float d_x1[NN * DD];

// ============================================================
// Kernel 1: g_l = xin @ W_l, g_r = xin @ W_r  (xin [384,512], W [512,512])
// Tile: BM=32, BN=64, BK=32. Grid (16,12): bx<8 -> W_l cols, bx>=8 -> W_r.
// ============================================================
__global__ __launch_bounds__(256) void gemm_kernel(
    const float* __restrict__ xin_ext, int use_x1,
    const float* __restrict__ Wl, const float* __restrict__ Wr)
{
    const float* xin = use_x1 ? d_x1 : xin_ext;
    __shared__ float As[32][33];
    __shared__ float Bs[32][64];

    int tid = threadIdx.x;
    int bx  = blockIdx.x;               // 0..15
    int i0  = blockIdx.y * 32;
    int isL = (bx < 8);
    int c0  = (bx & 7) * 64;
    const float* W   = isL ? Wl : Wr;
    float*       outp = isL ? d_gl : d_gr;

    int row_t = tid >> 4;               // 0..15
    int col_t = tid & 15;               // 0..15

    int ar = tid >> 3;                  // 0..31  (A tile load)
    int ac = (tid & 7) * 4;
    int br0 = tid >> 4,          bc0 = (tid & 15) * 4;           // B tile load part 0
    int br1 = (tid + 256) >> 4,  bc1 = ((tid + 256) & 15) * 4;   // part 1

    float acc00=0,acc01=0,acc02=0,acc03=0;
    float acc10=0,acc11=0,acc12=0,acc13=0;

    for (int k0 = 0; k0 < DD; k0 += 32) {
        float4 av = *(const float4*)&xin[(i0 + ar) * DD + k0 + ac];
        As[ar][ac+0] = av.x; As[ar][ac+1] = av.y;
        As[ar][ac+2] = av.z; As[ar][ac+3] = av.w;
        *(float4*)&Bs[br0][bc0] = *(const float4*)&W[(k0 + br0) * DD + c0 + bc0];
        *(float4*)&Bs[br1][bc1] = *(const float4*)&W[(k0 + br1) * DD + c0 + bc1];
        __syncthreads();
        #pragma unroll
        for (int k = 0; k < 32; k++) {
            float a0 = As[row_t][k];
            float a1 = As[row_t + 16][k];
            float4 b = *(float4*)&Bs[k][col_t * 4];
            acc00 = fmaf(a0, b.x, acc00); acc01 = fmaf(a0, b.y, acc01);
            acc02 = fmaf(a0, b.z, acc02); acc03 = fmaf(a0, b.w, acc03);
            acc10 = fmaf(a1, b.x, acc10); acc11 = fmaf(a1, b.y, acc11);
            acc12 = fmaf(a1, b.z, acc12); acc13 = fmaf(a1, b.w, acc13);
        }
        __syncthreads();
    }
    *(float4*)&outp[(i0 + row_t)      * DD + c0 + col_t * 4] = make_float4(acc00,acc01,acc02,acc03);
    *(float4*)&outp[(i0 + row_t + 16) * DD + c0 + col_t * 4] = make_float4(acc10,acc11,acc12,acc13);
}

// ============================================================
// Kernel 2: logits. E[h][i][j] = mask ? sum_f a_f * LReLU(gr[i,h,f]+gl[j,h,f]) : -1e30
// Grid (12 jtiles, 12 itiles, 8 heads), 256 threads.
// ============================================================
__global__ __launch_bounds__(256) void logits_kernel(
    const float* __restrict__ a_vec, const int* __restrict__ adj)
{
    __shared__ float grs[32 * 65];
    __shared__ float gls[32 * 65];
    __shared__ float as[64];

    int tid = threadIdx.x;
    int j0 = blockIdx.x * 32;
    int i0 = blockIdx.y * 32;
    int h  = blockIdx.z;

    if (tid < 64) as[tid] = a_vec[tid];
    #pragma unroll
    for (int p = 0; p < 8; p++) {
        int l = tid + p * 256;
        int r = l >> 6, f = l & 63;
        grs[r * 65 + f] = d_gr[(i0 + r) * DD + h * FF + f];
        gls[r * 65 + f] = d_gl[(j0 + r) * DD + h * FF + f];
    }
    __syncthreads();

    int jj = tid & 31;
    int ib = tid >> 5;        // 0..7
    float acc0 = 0, acc1 = 0, acc2 = 0, acc3 = 0;
    #pragma unroll 4
    for (int f = 0; f < 64; f++) {
        float glv = gls[jj * 65 + f];
        float af  = as[f];
        float v;
        v = grs[(ib +  0) * 65 + f] + glv; v = v > 0.f ? v : 0.2f * v; acc0 = fmaf(af, v, acc0);
        v = grs[(ib +  8) * 65 + f] + glv; v = v > 0.f ? v : 0.2f * v; acc1 = fmaf(af, v, acc1);
        v = grs[(ib + 16) * 65 + f] + glv; v = v > 0.f ? v : 0.2f * v; acc2 = fmaf(af, v, acc2);
        v = grs[(ib + 24) * 65 + f] + glv; v = v > 0.f ? v : 0.2f * v; acc3 = fmaf(af, v, acc3);
    }
    int j = j0 + jj;
    float accs[4] = {acc0, acc1, acc2, acc3};
    #pragma unroll
    for (int q = 0; q < 4; q++) {
        int i = i0 + ib + q * 8;
        int m = adj[i * NN + j];
        float e = (m != 0 || i == j) ? accs[q] : -1e30f;
        d_E[(h * NN + i) * NN + j] = e;
    }
}

// ============================================================
// Kernel 3: in-place softmax over j of E[h][i][:]. Grid (384, 8), 128 threads.
// ============================================================
__global__ __launch_bounds__(128) void softmax_kernel()
{
    int i = blockIdx.x, h = blockIdx.y;
    float* row = &d_E[(h * NN + i) * NN];
    int tid = threadIdx.x;

    float v[3];
    float m = -1e38f;
    #pragma unroll
    for (int p = 0; p < 3; p++) { v[p] = row[tid + p * 128]; m = fmaxf(m, v[p]); }
    #pragma unroll
    for (int o = 16; o > 0; o >>= 1) m = fmaxf(m, __shfl_xor_sync(0xffffffffu, m, o));
    __shared__ float sm[4];
    if ((tid & 31) == 0) sm[tid >> 5] = m;
    __syncthreads();
    float M = fmaxf(fmaxf(sm[0], sm[1]), fmaxf(sm[2], sm[3]));

    float s = 0.f;
    #pragma unroll
    for (int p = 0; p < 3; p++) { v[p] = expf(v[p] - M); s += v[p]; }
    #pragma unroll
    for (int o = 16; o > 0; o >>= 1) s += __shfl_xor_sync(0xffffffffu, s, o);
    __shared__ float ss[4];
    if ((tid & 31) == 0) ss[tid >> 5] = s;
    __syncthreads();
    float inv = 1.f / (ss[0] + ss[1] + ss[2] + ss[3]);
    #pragma unroll
    for (int p = 0; p < 3; p++) row[tid + p * 128] = v[p] * inv;
}

// ============================================================
// Kernel 4: out[i, h*64+f] = xin[...] + act( sum_j att[h,i,j] * g_r[j, h*64+f] )
// Grid (12 itiles, 8 heads), 256 threads.
// ============================================================
__global__ __launch_bounds__(256) void aggregate_kernel(
    const float* __restrict__ xin_ext, int use_x1_in,
    float* __restrict__ out_ext, int write_x1, int do_elu)
{
    const float* xin  = use_x1_in ? d_x1 : xin_ext;
    float*       outp = write_x1  ? d_x1 : out_ext;

    __shared__ float att_s[32 * 33];
    __shared__ float grs[32 * 64];

    int tid = threadIdx.x;
    int i0 = blockIdx.x * 32;
    int h  = blockIdx.y;
    int f  = tid & 63;
    int ib = tid >> 6;      // 0..3

    float acc[8] = {0,0,0,0,0,0,0,0};

    for (int j0 = 0; j0 < NN; j0 += 32) {
        #pragma unroll
        for (int p = 0; p < 4; p++) {
            int l = tid + p * 256;
            int ii = l >> 5, jj = l & 31;
            att_s[ii * 33 + jj] = d_E[(h * NN + i0 + ii) * NN + j0 + jj];
        }
        #pragma unroll
        for (int p = 0; p < 8; p++) {
            int l = tid + p * 256;
            int jj = l >> 6, ff = l & 63;
            grs[jj * 64 + ff] = d_gr[(j0 + jj) * DD + h * FF + ff];
        }
        __syncthreads();
        #pragma unroll 8
        for (int jj = 0; jj < 32; jj++) {
            float gv = grs[jj * 64 + f];
            #pragma unroll
            for (int q = 0; q < 8; q++)
                acc[q] = fmaf(att_s[(ib + q * 4) * 33 + jj], gv, acc[q]);
        }
        __syncthreads();
    }
    #pragma unroll
    for (int q = 0; q < 8; q++) {
        int i = i0 + ib + q * 4;
        float val = acc[q];
        if (do_elu) val = val > 0.f ? val : expm1f(val);
        outp[i * DD + h * FF + f] = xin[i * DD + h * FF + f] + val;
    }
}

// ============================================================
extern "C" void kernel_launch(void* const* d_in, const int* in_sizes, int n_in,
                              void* d_out, int out_size)
{
    const float* x   = (const float*)d_in[0];
    const int*   adj = (const int*)  d_in[1];
    const float* Wl0 = (const float*)d_in[2];
    const float* Wr0 = (const float*)d_in[3];
    const float* a0  = (const float*)d_in[4];
    const float* Wl1 = (const float*)d_in[5];
    const float* Wr1 = (const float*)d_in[6];
    const float* a1  = (const float*)d_in[7];
    float* out = (float*)d_out;

    dim3 gg(16, 12);            // gemm
    dim3 glg(12, 12, 8);        // logits
    dim3 gs(384, 8);            // softmax
    dim3 ga(12, 8);             // aggregate

    // ---- layer 0 ----
    gemm_kernel<<<gg, 256>>>(x, 0, Wl0, Wr0);
    logits_kernel<<<glg, 256>>>(a0, adj);
    softmax_kernel<<<gs, 128>>>();
    aggregate_kernel<<<ga, 256>>>(x, 0, nullptr, /*write_x1=*/1, /*elu=*/1);

    // ---- layer 1 ----
    gemm_kernel<<<gg, 256>>>(nullptr, 1, Wl1, Wr1);
    logits_kernel<<<glg, 256>>>(a1, adj);
    softmax_kernel<<<gs, 128>>>();
    aggregate_kernel<<<ga, 256>>>(nullptr, 1, out, /*write_x1=*/0, /*elu=*/0);
}

// round 4
// speedup vs baseline: 1.4347x; 1.4347x over previous
#include <cuda_runtime.h>
#include <math.h>

#define NN 384
#define DD 512
#define HH 8
#define FF 64
#define SPL 4

// ---- scratch (no allocations allowed) ----
__device__ float d_gl[NN * DD];
__device__ float d_gr[NN * DD];
__device__ float d_E[HH * NN * NN];
__device__ float d_x1[NN * DD];
__device__ float d_rvec[HH * NN];   // r[h,i] = sum_f a_f * gr[i,h,f]
__device__ float d_lvec[HH * NN];   // l[h,j] = sum_f a_f * gl[j,h,f]
__device__ float d_part[SPL * NN * DD];

// ============================================================
// Kernel 1: g_l = xin @ W_l, g_r = xin @ W_r  (xin [384,512], W [512,512])
// Tile: BM=32, BN=64, BK=32. Grid (16,12): bx<8 -> W_l cols, bx>=8 -> W_r.
// Epilogue: fused rank-1 projections r/l = sum_f a_f * g[:,h,f].
// ============================================================
__global__ __launch_bounds__(256) void gemm_kernel(
    const float* __restrict__ xin_ext, int use_x1,
    const float* __restrict__ Wl, const float* __restrict__ Wr,
    const float* __restrict__ a_vec)
{
    const float* xin = use_x1 ? d_x1 : xin_ext;
    __shared__ float As[32][33];
    __shared__ float Bs[32][64];

    int tid = threadIdx.x;
    int bx  = blockIdx.x;               // 0..15
    int i0  = blockIdx.y * 32;
    int isL = (bx < 8);
    int c0  = (bx & 7) * 64;
    const float* W   = isL ? Wl : Wr;
    float*       outp = isL ? d_gl : d_gr;

    int row_t = tid >> 4;               // 0..15
    int col_t = tid & 15;               // 0..15

    int ar = tid >> 3;                  // 0..31  (A tile load)
    int ac = (tid & 7) * 4;
    int br0 = tid >> 4,          bc0 = (tid & 15) * 4;
    int br1 = (tid + 256) >> 4,  bc1 = ((tid + 256) & 15) * 4;

    float acc00=0,acc01=0,acc02=0,acc03=0;
    float acc10=0,acc11=0,acc12=0,acc13=0;

    for (int k0 = 0; k0 < DD; k0 += 32) {
        float4 av = *(const float4*)&xin[(i0 + ar) * DD + k0 + ac];
        As[ar][ac+0] = av.x; As[ar][ac+1] = av.y;
        As[ar][ac+2] = av.z; As[ar][ac+3] = av.w;
        *(float4*)&Bs[br0][bc0] = *(const float4*)&W[(k0 + br0) * DD + c0 + bc0];
        *(float4*)&Bs[br1][bc1] = *(const float4*)&W[(k0 + br1) * DD + c0 + bc1];
        __syncthreads();
        #pragma unroll
        for (int k = 0; k < 32; k++) {
            float a0 = As[row_t][k];
            float a1 = As[row_t + 16][k];
            float4 b = *(float4*)&Bs[k][col_t * 4];
            acc00 = fmaf(a0, b.x, acc00); acc01 = fmaf(a0, b.y, acc01);
            acc02 = fmaf(a0, b.z, acc02); acc03 = fmaf(a0, b.w, acc03);
            acc10 = fmaf(a1, b.x, acc10); acc11 = fmaf(a1, b.y, acc11);
            acc12 = fmaf(a1, b.z, acc12); acc13 = fmaf(a1, b.w, acc13);
        }
        __syncthreads();
    }
    *(float4*)&outp[(i0 + row_t)      * DD + c0 + col_t * 4] = make_float4(acc00,acc01,acc02,acc03);
    *(float4*)&outp[(i0 + row_t + 16) * DD + c0 + col_t * 4] = make_float4(acc10,acc11,acc12,acc13);

    // ---- fused r/l projection: this block owns head (bx&7), f = col_t*4..+3 ----
    float4 aa = *(const float4*)&a_vec[col_t * 4];
    float p0 = acc00*aa.x + acc01*aa.y + acc02*aa.z + acc03*aa.w;
    float p1 = acc10*aa.x + acc11*aa.y + acc12*aa.z + acc13*aa.w;
    #pragma unroll
    for (int o = 8; o > 0; o >>= 1) {
        p0 += __shfl_xor_sync(0xffffffffu, p0, o);
        p1 += __shfl_xor_sync(0xffffffffu, p1, o);
    }
    if ((tid & 15) == 0) {
        int h = bx & 7;
        float* dst = isL ? d_lvec : d_rvec;
        dst[h * NN + i0 + row_t]      = p0;
        dst[h * NN + i0 + row_t + 16] = p1;
    }
}

// ============================================================
// Kernel 2: logits via LReLU(v) = 0.6v + 0.4|v| decomposition:
// E[h][i][j] = 0.6*(r[h,i]+l[h,j]) + 0.4*sum_f a_f*|gr[i,h,f]+gl[j,h,f]|
// Grid (12 jtiles, 12 itiles, 8 heads), 128 threads, 8 rows/thread.
// ============================================================
__global__ __launch_bounds__(128) void logits_kernel(
    const float* __restrict__ a_vec, const int* __restrict__ adj)
{
    __shared__ float grs[32 * 64];
    __shared__ float gls[32 * 65];
    __shared__ float as[64];
    __shared__ float rvs[32];
    __shared__ float lvs[32];

    int tid = threadIdx.x;
    int j0 = blockIdx.x * 32;
    int i0 = blockIdx.y * 32;
    int h  = blockIdx.z;

    if (tid < 64)       as[tid]        = a_vec[tid];
    else if (tid < 96)  rvs[tid - 64]  = d_rvec[h * NN + i0 + (tid - 64)];
    else                lvs[tid - 96]  = d_lvec[h * NN + j0 + (tid - 96)];

    #pragma unroll
    for (int p = 0; p < 4; p++) {
        int idx = tid + p * 128;
        int r = idx >> 4, f4 = (idx & 15) * 4;
        float4 v = *(const float4*)&d_gr[(i0 + r) * DD + h * FF + f4];
        *(float4*)&grs[r * 64 + f4] = v;
        float4 w = *(const float4*)&d_gl[(j0 + r) * DD + h * FF + f4];
        gls[r*65 + f4+0] = w.x; gls[r*65 + f4+1] = w.y;
        gls[r*65 + f4+2] = w.z; gls[r*65 + f4+3] = w.w;
    }
    __syncthreads();

    int jj = tid & 31;
    int ib = tid >> 5;        // 0..3 (uniform across a warp -> grs reads broadcast)
    float acc[8] = {0,0,0,0,0,0,0,0};
    #pragma unroll 8
    for (int f = 0; f < 64; f++) {
        float glv = gls[jj * 65 + f];
        float af  = as[f];
        #pragma unroll
        for (int q = 0; q < 8; q++) {
            float v = grs[(ib + q * 4) * 64 + f] + glv;
            acc[q] = fmaf(af, fabsf(v), acc[q]);
        }
    }
    float lvj = lvs[jj];
    int j = j0 + jj;
    #pragma unroll
    for (int q = 0; q < 8; q++) {
        int i = i0 + ib + q * 4;
        float e = 0.6f * (rvs[ib + q * 4] + lvj) + 0.4f * acc[q];
        int m = adj[i * NN + j];
        d_E[(h * NN + i) * NN + j] = (m != 0 || i == j) ? e : -1e30f;
    }
}

// ============================================================
// Kernel 3: in-place softmax over j of E[h][i][:]. Grid (384, 8), 128 threads.
// ============================================================
__global__ __launch_bounds__(128) void softmax_kernel()
{
    int i = blockIdx.x, h = blockIdx.y;
    float* row = &d_E[(h * NN + i) * NN];
    int tid = threadIdx.x;

    float v[3];
    float m = -1e38f;
    #pragma unroll
    for (int p = 0; p < 3; p++) { v[p] = row[tid + p * 128]; m = fmaxf(m, v[p]); }
    #pragma unroll
    for (int o = 16; o > 0; o >>= 1) m = fmaxf(m, __shfl_xor_sync(0xffffffffu, m, o));
    __shared__ float sm[4];
    if ((tid & 31) == 0) sm[tid >> 5] = m;
    __syncthreads();
    float M = fmaxf(fmaxf(sm[0], sm[1]), fmaxf(sm[2], sm[3]));

    float s = 0.f;
    #pragma unroll
    for (int p = 0; p < 3; p++) { v[p] = expf(v[p] - M); s += v[p]; }
    #pragma unroll
    for (int o = 16; o > 0; o >>= 1) s += __shfl_xor_sync(0xffffffffu, s, o);
    __shared__ float ss[4];
    if ((tid & 31) == 0) ss[tid >> 5] = s;
    __syncthreads();
    float inv = 1.f / (ss[0] + ss[1] + ss[2] + ss[3]);
    #pragma unroll
    for (int p = 0; p < 3; p++) row[tid + p * 128] = v[p] * inv;
}

// ============================================================
// Kernel 4a: split-K aggregation partials.
// part[s][i, h*64+f] = sum_{j in split s} att[h,i,j] * g_r[j, h*64+f]
// Grid (12 itiles, 8 heads, SPL splits), 128 threads, 4x4 micro-tile.
// ============================================================
__global__ __launch_bounds__(128) void aggregate_kernel()
{
    __shared__ float att_s[32 * 40];   // stride 40 floats: 16B-aligned rows, broadcast reads
    __shared__ float gr_s[32 * 64];

    int tid = threadIdx.x;
    int i0 = blockIdx.x * 32;
    int h  = blockIdx.y;
    int s  = blockIdx.z;
    int J0 = s * (NN / SPL);           // 96 j's per split

    int ib = tid >> 4;                 // 0..7
    int fg = tid & 15;
    int f  = fg * 4;

    float acc[4][4] = {};

    #pragma unroll 1
    for (int t = 0; t < (NN / SPL) / 32; t++) {
        int j0 = J0 + t * 32;
        #pragma unroll
        for (int q = 0; q < 2; q++) {
            int idx = tid + q * 128;
            int ii = idx >> 3, jc = (idx & 7) * 4;
            float4 v = *(const float4*)&d_E[(h * NN + i0 + ii) * NN + j0 + jc];
            *(float4*)&att_s[ii * 40 + jc] = v;
        }
        #pragma unroll
        for (int p = 0; p < 4; p++) {
            int idx = tid + p * 128;
            int jj = idx >> 4, ff = (idx & 15) * 4;
            *(float4*)&gr_s[jj * 64 + ff] =
                *(const float4*)&d_gr[(j0 + jj) * DD + h * FF + ff];
        }
        __syncthreads();
        #pragma unroll
        for (int jj = 0; jj < 32; jj++) {
            float4 g = *(float4*)&gr_s[jj * 64 + f];
            #pragma unroll
            for (int q = 0; q < 4; q++) {
                float av = att_s[(ib + q * 8) * 40 + jj];
                acc[q][0] = fmaf(av, g.x, acc[q][0]);
                acc[q][1] = fmaf(av, g.y, acc[q][1]);
                acc[q][2] = fmaf(av, g.z, acc[q][2]);
                acc[q][3] = fmaf(av, g.w, acc[q][3]);
            }
        }
        __syncthreads();
    }
    #pragma unroll
    for (int q = 0; q < 4; q++) {
        int i = i0 + ib + q * 8;
        *(float4*)&d_part[(s * NN + i) * DD + h * FF + f] =
            make_float4(acc[q][0], acc[q][1], acc[q][2], acc[q][3]);
    }
}

// ============================================================
// Kernel 4b: finalize. out = xin + act(sum_s part[s])
// Grid 192, 256 threads, float4 per thread.
// ============================================================
__global__ __launch_bounds__(256) void finalize_kernel(
    const float* __restrict__ xin_ext, int use_x1_in,
    float* __restrict__ out_ext, int write_x1, int do_elu)
{
    const float* xin  = use_x1_in ? d_x1 : xin_ext;
    float*       outp = write_x1  ? d_x1 : out_ext;

    int e = (blockIdx.x * 256 + threadIdx.x) * 4;
    float4 s0 = *(const float4*)&d_part[0 * NN * DD + e];
    float4 s1 = *(const float4*)&d_part[1 * NN * DD + e];
    float4 s2 = *(const float4*)&d_part[2 * NN * DD + e];
    float4 s3 = *(const float4*)&d_part[3 * NN * DD + e];
    float4 xv = *(const float4*)&xin[e];

    float v0 = (s0.x + s1.x) + (s2.x + s3.x);
    float v1 = (s0.y + s1.y) + (s2.y + s3.y);
    float v2 = (s0.z + s1.z) + (s2.z + s3.z);
    float v3 = (s0.w + s1.w) + (s2.w + s3.w);
    if (do_elu) {
        v0 = v0 > 0.f ? v0 : expm1f(v0);
        v1 = v1 > 0.f ? v1 : expm1f(v1);
        v2 = v2 > 0.f ? v2 : expm1f(v2);
        v3 = v3 > 0.f ? v3 : expm1f(v3);
    }
    *(float4*)&outp[e] = make_float4(xv.x + v0, xv.y + v1, xv.z + v2, xv.w + v3);
}

// ============================================================
extern "C" void kernel_launch(void* const* d_in, const int* in_sizes, int n_in,
                              void* d_out, int out_size)
{
    const float* x   = (const float*)d_in[0];
    const int*   adj = (const int*)  d_in[1];
    const float* Wl0 = (const float*)d_in[2];
    const float* Wr0 = (const float*)d_in[3];
    const float* a0  = (const float*)d_in[4];
    const float* Wl1 = (const float*)d_in[5];
    const float* Wr1 = (const float*)d_in[6];
    const float* a1  = (const float*)d_in[7];
    float* out = (float*)d_out;

    dim3 gg(16, 12);            // gemm
    dim3 glg(12, 12, 8);        // logits
    dim3 gs(384, 8);            // softmax
    dim3 ga(12, 8, SPL);        // aggregate partials
    int  gf = (NN * DD) / (256 * 4);   // finalize: 192 blocks

    // ---- layer 0 ----
    gemm_kernel<<<gg, 256>>>(x, 0, Wl0, Wr0, a0);
    logits_kernel<<<glg, 128>>>(a0, adj);
    softmax_kernel<<<gs, 128>>>();
    aggregate_kernel<<<ga, 128>>>();
    finalize_kernel<<<gf, 256>>>(x, 0, nullptr, /*write_x1=*/1, /*elu=*/1);

    // ---- layer 1 ----
    gemm_kernel<<<gg, 256>>>(nullptr, 1, Wl1, Wr1, a1);
    logits_kernel<<<glg, 128>>>(a1, adj);
    softmax_kernel<<<gs, 128>>>();
    aggregate_kernel<<<ga, 128>>>();
    finalize_kernel<<<gf, 256>>>(nullptr, 1, out, /*write_x1=*/0, /*elu=*/0);
}

// round 5
// speedup vs baseline: 1.6647x; 1.1603x over previous
#include <cuda_runtime.h>
#include <math.h>

#define NN 384
#define DD 512
#define HH 8
#define FF 64
#define SPL 6

// ---- scratch (no allocations allowed) ----
__device__ float d_gl[NN * DD];
__device__ float d_gr[NN * DD];
__device__ float d_E[HH * NN * NN];
__device__ float d_x1[NN * DD];
__device__ float d_rvec[HH * NN];   // r[h,i] = sum_f a_f * gr[i,h,f]
__device__ float d_lvec[HH * NN];   // l[h,j] = sum_f a_f * gl[j,h,f]
__device__ float d_part[SPL * NN * DD];

// ============================================================
// Kernel 1: g_l = xin @ W_l, g_r = xin @ W_r  (xin [384,512], W [512,512])
// Tile: BM=16, BN=64, BK=32, 128 threads, 2x4 micro-tile.
// Grid (16, 24): bx<8 -> W_l cols, bx>=8 -> W_r. 384 blocks -> balanced waves.
// Epilogue: fused rank-1 projections r/l = sum_f a_f * g[:,h,f].
// ============================================================
__global__ __launch_bounds__(128) void gemm_kernel(
    const float* __restrict__ xin_ext, int use_x1,
    const float* __restrict__ Wl, const float* __restrict__ Wr,
    const float* __restrict__ a_vec)
{
    const float* xin = use_x1 ? d_x1 : xin_ext;
    __shared__ float As[16][33];
    __shared__ float Bs[32][64];

    int tid = threadIdx.x;
    int bx  = blockIdx.x;               // 0..15
    int i0  = blockIdx.y * 16;          // 24 i-tiles
    int isL = (bx < 8);
    int c0  = (bx & 7) * 64;
    const float* W    = isL ? Wl : Wr;
    float*       outp = isL ? d_gl : d_gr;

    int row_t = tid >> 4;               // 0..7
    int col_t = tid & 15;               // 0..15

    int ar = tid >> 3;                  // 0..15  (A tile load)
    int ac = (tid & 7) * 4;
    int br = tid >> 4;                  // 0..7   (B tile load, 4 rounds of 8 rows)
    int bc = (tid & 15) * 4;

    float acc00=0,acc01=0,acc02=0,acc03=0;
    float acc10=0,acc11=0,acc12=0,acc13=0;

    for (int k0 = 0; k0 < DD; k0 += 32) {
        float4 av = *(const float4*)&xin[(i0 + ar) * DD + k0 + ac];
        As[ar][ac+0] = av.x; As[ar][ac+1] = av.y;
        As[ar][ac+2] = av.z; As[ar][ac+3] = av.w;
        #pragma unroll
        for (int r = 0; r < 4; r++) {
            *(float4*)&Bs[br + r * 8][bc] =
                *(const float4*)&W[(k0 + br + r * 8) * DD + c0 + bc];
        }
        __syncthreads();
        #pragma unroll
        for (int k = 0; k < 32; k++) {
            float a0 = As[row_t][k];
            float a1 = As[row_t + 8][k];
            float4 b = *(float4*)&Bs[k][col_t * 4];
            acc00 = fmaf(a0, b.x, acc00); acc01 = fmaf(a0, b.y, acc01);
            acc02 = fmaf(a0, b.z, acc02); acc03 = fmaf(a0, b.w, acc03);
            acc10 = fmaf(a1, b.x, acc10); acc11 = fmaf(a1, b.y, acc11);
            acc12 = fmaf(a1, b.z, acc12); acc13 = fmaf(a1, b.w, acc13);
        }
        __syncthreads();
    }
    *(float4*)&outp[(i0 + row_t)     * DD + c0 + col_t * 4] = make_float4(acc00,acc01,acc02,acc03);
    *(float4*)&outp[(i0 + row_t + 8) * DD + c0 + col_t * 4] = make_float4(acc10,acc11,acc12,acc13);

    // ---- fused r/l projection: this block owns head (bx&7), f = col_t*4..+3 ----
    float4 aa = *(const float4*)&a_vec[col_t * 4];
    float p0 = acc00*aa.x + acc01*aa.y + acc02*aa.z + acc03*aa.w;
    float p1 = acc10*aa.x + acc11*aa.y + acc12*aa.z + acc13*aa.w;
    #pragma unroll
    for (int o = 8; o > 0; o >>= 1) {
        p0 += __shfl_xor_sync(0xffffffffu, p0, o);
        p1 += __shfl_xor_sync(0xffffffffu, p1, o);
    }
    if ((tid & 15) == 0) {
        int h = bx & 7;
        float* dst = isL ? d_lvec : d_rvec;
        dst[h * NN + i0 + row_t]     = p0;
        dst[h * NN + i0 + row_t + 8] = p1;
    }
}

// ============================================================
// Kernel 2: logits via LReLU(v) = 0.6v + 0.4|v| decomposition:
// E[h][i][j] = 0.6*(r[h,i]+l[h,j]) + 0.4*sum_f a_f*|gr[i,h,f]+gl[j,h,f]|
// Grid (12 jtiles, 12 itiles, 8 heads), 128 threads, 8 rows/thread, float2 f-step.
// ============================================================
__global__ __launch_bounds__(128) void logits_kernel(
    const float* __restrict__ a_vec, const int* __restrict__ adj)
{
    __shared__ float grs[32 * 64];
    __shared__ float gls[32 * 66];   // stride 66: conflict-free LDS.64 at stride jj
    __shared__ float as[64];
    __shared__ float rvs[32];
    __shared__ float lvs[32];

    int tid = threadIdx.x;
    int j0 = blockIdx.x * 32;
    int i0 = blockIdx.y * 32;
    int h  = blockIdx.z;

    if (tid < 64)       as[tid]        = a_vec[tid];
    else if (tid < 96)  rvs[tid - 64]  = d_rvec[h * NN + i0 + (tid - 64)];
    else                lvs[tid - 96]  = d_lvec[h * NN + j0 + (tid - 96)];

    #pragma unroll
    for (int p = 0; p < 4; p++) {
        int idx = tid + p * 128;
        int r = idx >> 4, f4 = (idx & 15) * 4;
        float4 v = *(const float4*)&d_gr[(i0 + r) * DD + h * FF + f4];
        *(float4*)&grs[r * 64 + f4] = v;
        float4 w = *(const float4*)&d_gl[(j0 + r) * DD + h * FF + f4];
        *(float2*)&gls[r * 66 + f4]     = make_float2(w.x, w.y);
        *(float2*)&gls[r * 66 + f4 + 2] = make_float2(w.z, w.w);
    }
    __syncthreads();

    int jj = tid & 31;
    int ib = tid >> 5;        // 0..3 (uniform across a warp -> grs reads broadcast)
    float acc[8] = {0,0,0,0,0,0,0,0};
    #pragma unroll 8
    for (int f = 0; f < 64; f += 2) {
        float2 gl2 = *(float2*)&gls[jj * 66 + f];
        float2 a2  = *(float2*)&as[f];
        #pragma unroll
        for (int q = 0; q < 8; q++) {
            float2 g2 = *(float2*)&grs[(ib + q * 4) * 64 + f];
            float v0 = g2.x + gl2.x;
            float v1 = g2.y + gl2.y;
            acc[q] = fmaf(a2.x, fabsf(v0), acc[q]);
            acc[q] = fmaf(a2.y, fabsf(v1), acc[q]);
        }
    }
    float lvj = lvs[jj];
    int j = j0 + jj;
    #pragma unroll
    for (int q = 0; q < 8; q++) {
        int i = i0 + ib + q * 4;
        float e = 0.6f * (rvs[ib + q * 4] + lvj) + 0.4f * acc[q];
        int m = adj[i * NN + j];
        d_E[(h * NN + i) * NN + j] = (m != 0 || i == j) ? e : -1e30f;
    }
}

// ============================================================
// Kernel 3: in-place softmax over j of E[h][i][:]. Grid (384, 8), 128 threads.
// ============================================================
__global__ __launch_bounds__(128) void softmax_kernel()
{
    int i = blockIdx.x, h = blockIdx.y;
    float* row = &d_E[(h * NN + i) * NN];
    int tid = threadIdx.x;

    float v[3];
    float m = -1e38f;
    #pragma unroll
    for (int p = 0; p < 3; p++) { v[p] = row[tid + p * 128]; m = fmaxf(m, v[p]); }
    #pragma unroll
    for (int o = 16; o > 0; o >>= 1) m = fmaxf(m, __shfl_xor_sync(0xffffffffu, m, o));
    __shared__ float sm[4];
    if ((tid & 31) == 0) sm[tid >> 5] = m;
    __syncthreads();
    float M = fmaxf(fmaxf(sm[0], sm[1]), fmaxf(sm[2], sm[3]));

    float s = 0.f;
    #pragma unroll
    for (int p = 0; p < 3; p++) { v[p] = expf(v[p] - M); s += v[p]; }
    #pragma unroll
    for (int o = 16; o > 0; o >>= 1) s += __shfl_xor_sync(0xffffffffu, s, o);
    __shared__ float ss[4];
    if ((tid & 31) == 0) ss[tid >> 5] = s;
    __syncthreads();
    float inv = 1.f / (ss[0] + ss[1] + ss[2] + ss[3]);
    #pragma unroll
    for (int p = 0; p < 3; p++) row[tid + p * 128] = v[p] * inv;
}

// ============================================================
// Kernel 4a: split-K aggregation partials.
// part[s][i, h*64+f] = sum_{j in split s} att[h,i,j] * g_r[j, h*64+f]
// Grid (12 itiles, 8 heads, SPL=6 splits of 64 j), 128 threads, 4x4 micro-tile.
// ============================================================
__global__ __launch_bounds__(128) void aggregate_kernel()
{
    __shared__ float att_s[32 * 40];   // 16B-aligned rows, broadcast reads
    __shared__ float gr_s[32 * 64];

    int tid = threadIdx.x;
    int i0 = blockIdx.x * 32;
    int h  = blockIdx.y;
    int s  = blockIdx.z;
    int J0 = s * (NN / SPL);           // 64 j's per split

    int ib = tid >> 4;                 // 0..7
    int f  = (tid & 15) * 4;

    float acc[4][4] = {};

    #pragma unroll 1
    for (int t = 0; t < (NN / SPL) / 32; t++) {
        int j0 = J0 + t * 32;
        #pragma unroll
        for (int q = 0; q < 2; q++) {
            int idx = tid + q * 128;
            int ii = idx >> 3, jc = (idx & 7) * 4;
            float4 v = *(const float4*)&d_E[(h * NN + i0 + ii) * NN + j0 + jc];
            *(float4*)&att_s[ii * 40 + jc] = v;
        }
        #pragma unroll
        for (int p = 0; p < 4; p++) {
            int idx = tid + p * 128;
            int jj = idx >> 4, ff = (idx & 15) * 4;
            *(float4*)&gr_s[jj * 64 + ff] =
                *(const float4*)&d_gr[(j0 + jj) * DD + h * FF + ff];
        }
        __syncthreads();
        #pragma unroll
        for (int jj = 0; jj < 32; jj++) {
            float4 g = *(float4*)&gr_s[jj * 64 + f];
            #pragma unroll
            for (int q = 0; q < 4; q++) {
                float av = att_s[(ib + q * 8) * 40 + jj];
                acc[q][0] = fmaf(av, g.x, acc[q][0]);
                acc[q][1] = fmaf(av, g.y, acc[q][1]);
                acc[q][2] = fmaf(av, g.z, acc[q][2]);
                acc[q][3] = fmaf(av, g.w, acc[q][3]);
            }
        }
        __syncthreads();
    }
    #pragma unroll
    for (int q = 0; q < 4; q++) {
        int i = i0 + ib + q * 8;
        *(float4*)&d_part[(s * NN + i) * DD + h * FF + f] =
            make_float4(acc[q][0], acc[q][1], acc[q][2], acc[q][3]);
    }
}

// ============================================================
// Kernel 4b: finalize. out = xin + act(sum_s part[s])
// Grid 192, 256 threads, float4 per thread.
// ============================================================
__global__ __launch_bounds__(256) void finalize_kernel(
    const float* __restrict__ xin_ext, int use_x1_in,
    float* __restrict__ out_ext, int write_x1, int do_elu)
{
    const float* xin  = use_x1_in ? d_x1 : xin_ext;
    float*       outp = write_x1  ? d_x1 : out_ext;

    int e = (blockIdx.x * 256 + threadIdx.x) * 4;
    float v0 = 0.f, v1 = 0.f, v2 = 0.f, v3 = 0.f;
    #pragma unroll
    for (int s = 0; s < SPL; s++) {
        float4 p = *(const float4*)&d_part[s * NN * DD + e];
        v0 += p.x; v1 += p.y; v2 += p.z; v3 += p.w;
    }
    float4 xv = *(const float4*)&xin[e];
    if (do_elu) {
        v0 = v0 > 0.f ? v0 : expm1f(v0);
        v1 = v1 > 0.f ? v1 : expm1f(v1);
        v2 = v2 > 0.f ? v2 : expm1f(v2);
        v3 = v3 > 0.f ? v3 : expm1f(v3);
    }
    *(float4*)&outp[e] = make_float4(xv.x + v0, xv.y + v1, xv.z + v2, xv.w + v3);
}

// ============================================================
extern "C" void kernel_launch(void* const* d_in, const int* in_sizes, int n_in,
                              void* d_out, int out_size)
{
    const float* x   = (const float*)d_in[0];
    const int*   adj = (const int*)  d_in[1];
    const float* Wl0 = (const float*)d_in[2];
    const float* Wr0 = (const float*)d_in[3];
    const float* a0  = (const float*)d_in[4];
    const float* Wl1 = (const float*)d_in[5];
    const float* Wr1 = (const float*)d_in[6];
    const float* a1  = (const float*)d_in[7];
    float* out = (float*)d_out;

    dim3 gg(16, 24);            // gemm: 384 blocks
    dim3 glg(12, 12, 8);        // logits
    dim3 gs(384, 8);            // softmax
    dim3 ga(12, 8, SPL);        // aggregate partials: 576 blocks
    int  gf = (NN * DD) / (256 * 4);   // finalize: 192 blocks

    // ---- layer 0 ----
    gemm_kernel<<<gg, 128>>>(x, 0, Wl0, Wr0, a0);
    logits_kernel<<<glg, 128>>>(a0, adj);
    softmax_kernel<<<gs, 128>>>();
    aggregate_kernel<<<ga, 128>>>();
    finalize_kernel<<<gf, 256>>>(x, 0, nullptr, /*write_x1=*/1, /*elu=*/1);

    // ---- layer 1 ----
    gemm_kernel<<<gg, 128>>>(nullptr, 1, Wl1, Wr1, a1);
    logits_kernel<<<glg, 128>>>(a1, adj);
    softmax_kernel<<<gs, 128>>>();
    aggregate_kernel<<<ga, 128>>>();
    finalize_kernel<<<gf, 256>>>(nullptr, 1, out, /*write_x1=*/0, /*elu=*/0);
}

// round 8
// speedup vs baseline: 1.9744x; 1.1861x over previous
#include <cuda_runtime.h>
#include <math.h>
#include <stdint.h>

#define NN 384
#define DD 512
#define HH 8
#define FF 64
#define SPL 12

// ---- scratch (no allocations allowed) ----
__device__ float d_gl[NN * DD];
__device__ float d_gr[NN * DD];
__device__ float d_E[HH * NN * NN];
__device__ float d_x1[NN * DD];
__device__ float d_rvec[HH * NN];   // r[h,i] = sum_f a_f * gr[i,h,f]
__device__ float d_lvec[HH * NN];   // l[h,j] = sum_f a_f * gl[j,h,f]
__device__ float d_part[SPL * NN * DD];

// ---- tf32 helpers ----
__device__ __forceinline__ uint32_t f2tf32(float x) {
    uint32_t r;
    asm("cvt.rna.tf32.f32 %0, %1;" : "=r"(r) : "f"(x));
    return r;
}
__device__ __forceinline__ void mma_tf32(float c[4], const uint32_t a[4],
                                         uint32_t b0, uint32_t b1) {
    asm volatile(
        "mma.sync.aligned.m16n8k8.row.col.f32.tf32.tf32.f32 "
        "{%0,%1,%2,%3}, {%4,%5,%6,%7}, {%8,%9}, {%0,%1,%2,%3};\n"
        : "+f"(c[0]), "+f"(c[1]), "+f"(c[2]), "+f"(c[3])
        : "r"(a[0]), "r"(a[1]), "r"(a[2]), "r"(a[3]), "r"(b0), "r"(b1));
}

// ============================================================
// Kernel 1: g_l = xin @ W_l, g_r = xin @ W_r via tf32x3 mma.sync.
// Block: 128 thr (4 warps, 2M x 2N), BM=32, BN=64, BK=32 stages, pipelined.
// Grid (16, 12): bx<8 -> W_l head bx, bx>=8 -> W_r head bx-8. 192 blocks.
// Epilogue: fused rank-1 projections r/l = sum_f a_f * g[:,h,f] (fp32).
// ============================================================
__global__ __launch_bounds__(128) void gemm_kernel(
    const float* __restrict__ xin_ext, int use_x1,
    const float* __restrict__ Wl, const float* __restrict__ Wr,
    const float* __restrict__ a_vec)
{
    const float* xin = use_x1 ? d_x1 : xin_ext;
    __shared__ float As[32][36];     // [m][k], rows 16B-aligned, frag-conflict-free
    __shared__ float Bs[32][68];     // [k][n], rows 16B-aligned, frag-conflict-free
    __shared__ float red[2][32];

    int tid  = threadIdx.x;
    int bx   = blockIdx.x;
    int i0   = blockIdx.y * 32;
    int isL  = (bx < 8);
    int c0   = (bx & 7) * 64;
    const float* W    = isL ? Wl : Wr;
    float*       outp = isL ? d_gl : d_gr;

    int warp  = tid >> 5;
    int lane  = tid & 31;
    int g     = lane >> 2;           // 0..7
    int tig   = lane & 3;            // 0..3
    int m0    = (warp & 1) * 16;
    int n0    = (warp >> 1) * 32;

    // staging coords
    int aRow0 = tid >> 3,            aCol = (tid & 7) * 4;     // + row 16 for second f4
    int bRow0 = tid >> 4,            bCol = (tid & 15) * 4;    // rows +8,+16,+24

    float c[4][4] = {};              // 4 n-tiles x 4 regs

    float4 ra0, ra1, rb0, rb1, rb2, rb3;
    // prologue loads (k0 = 0)
    ra0 = *(const float4*)&xin[(i0 + aRow0)      * DD + aCol];
    ra1 = *(const float4*)&xin[(i0 + aRow0 + 16) * DD + aCol];
    rb0 = *(const float4*)&W[(bRow0)      * DD + c0 + bCol];
    rb1 = *(const float4*)&W[(bRow0 +  8) * DD + c0 + bCol];
    rb2 = *(const float4*)&W[(bRow0 + 16) * DD + c0 + bCol];
    rb3 = *(const float4*)&W[(bRow0 + 24) * DD + c0 + bCol];

    for (int k0 = 0; k0 < DD; k0 += 32) {
        *(float4*)&As[aRow0][aCol]      = ra0;
        *(float4*)&As[aRow0 + 16][aCol] = ra1;
        *(float4*)&Bs[bRow0][bCol]      = rb0;
        *(float4*)&Bs[bRow0 +  8][bCol] = rb1;
        *(float4*)&Bs[bRow0 + 16][bCol] = rb2;
        *(float4*)&Bs[bRow0 + 24][bCol] = rb3;
        __syncthreads();

        int kn = k0 + 32;
        if (kn < DD) {
            ra0 = *(const float4*)&xin[(i0 + aRow0)      * DD + kn + aCol];
            ra1 = *(const float4*)&xin[(i0 + aRow0 + 16) * DD + kn + aCol];
            rb0 = *(const float4*)&W[(kn + bRow0)      * DD + c0 + bCol];
            rb1 = *(const float4*)&W[(kn + bRow0 +  8) * DD + c0 + bCol];
            rb2 = *(const float4*)&W[(kn + bRow0 + 16) * DD + c0 + bCol];
            rb3 = *(const float4*)&W[(kn + bRow0 + 24) * DD + c0 + bCol];
        }

        #pragma unroll
        for (int kc = 0; kc < 4; kc++) {
            int kb = kc * 8;
            float av[4];
            av[0] = As[m0 + g][kb + tig];
            av[1] = As[m0 + g + 8][kb + tig];
            av[2] = As[m0 + g][kb + tig + 4];
            av[3] = As[m0 + g + 8][kb + tig + 4];
            uint32_t ah[4], al[4];
            #pragma unroll
            for (int e = 0; e < 4; e++) {
                ah[e] = f2tf32(av[e]);
                al[e] = f2tf32(av[e] - __uint_as_float(ah[e]));
            }
            #pragma unroll
            for (int t = 0; t < 4; t++) {
                float b0f = Bs[kb + tig][n0 + t * 8 + g];
                float b1f = Bs[kb + tig + 4][n0 + t * 8 + g];
                uint32_t bh0 = f2tf32(b0f), bh1 = f2tf32(b1f);
                uint32_t bl0 = f2tf32(b0f - __uint_as_float(bh0));
                uint32_t bl1 = f2tf32(b1f - __uint_as_float(bh1));
                mma_tf32(c[t], ah, bh0, bh1);   // hi*hi
                mma_tf32(c[t], al, bh0, bh1);   // lo*hi
                mma_tf32(c[t], ah, bl0, bl1);   // hi*lo
            }
        }
        __syncthreads();
    }

    // ---- store g tile ----
    int r0 = i0 + m0 + g;
    int r1 = r0 + 8;
    #pragma unroll
    for (int t = 0; t < 4; t++) {
        int cc = c0 + n0 + t * 8 + 2 * tig;
        *(float2*)&outp[r0 * DD + cc] = make_float2(c[t][0], c[t][1]);
        *(float2*)&outp[r1 * DD + cc] = make_float2(c[t][2], c[t][3]);
    }

    // ---- fused rank-1 projection (head = bx&7; cols of this block are f 0..63) ----
    float p0 = 0.f, p1 = 0.f;
    #pragma unroll
    for (int t = 0; t < 4; t++) {
        int fc = n0 + t * 8 + 2 * tig;
        float av0 = a_vec[fc], av1 = a_vec[fc + 1];
        p0 = fmaf(av0, c[t][0], fmaf(av1, c[t][1], p0));
        p1 = fmaf(av0, c[t][2], fmaf(av1, c[t][3], p1));
    }
    p0 += __shfl_xor_sync(0xffffffffu, p0, 1);
    p0 += __shfl_xor_sync(0xffffffffu, p0, 2);
    p1 += __shfl_xor_sync(0xffffffffu, p1, 1);
    p1 += __shfl_xor_sync(0xffffffffu, p1, 2);
    if (tig == 0) {
        red[warp >> 1][m0 + g]     = p0;
        red[warp >> 1][m0 + 8 + g] = p1;
    }
    __syncthreads();
    if (tid < 32) {
        int h = bx & 7;
        float* dst = isL ? d_lvec : d_rvec;
        dst[h * NN + i0 + tid] = red[0][tid] + red[1][tid];
    }
}

// ============================================================
// Kernel 2: logits via LReLU(v) = 0.6v + 0.4|v| decomposition:
// E[h][i][j] = 0.6*(r[h,i]+l[h,j]) + 0.4*sum_f a_f*|gr[i,h,f]+gl[j,h,f]|
// Grid (12 jtiles, 12 itiles, 8 heads), 128 threads, 8 rows/thread, float2 f-step.
// ============================================================
__global__ __launch_bounds__(128) void logits_kernel(
    const float* __restrict__ a_vec, const int* __restrict__ adj)
{
    __shared__ float grs[32 * 64];
    __shared__ float gls[32 * 66];   // stride 66: conflict-free LDS.64 at stride jj
    __shared__ float as[64];
    __shared__ float rvs[32];
    __shared__ float lvs[32];

    int tid = threadIdx.x;
    int j0 = blockIdx.x * 32;
    int i0 = blockIdx.y * 32;
    int h  = blockIdx.z;

    if (tid < 64)       as[tid]        = a_vec[tid];
    else if (tid < 96)  rvs[tid - 64]  = d_rvec[h * NN + i0 + (tid - 64)];
    else                lvs[tid - 96]  = d_lvec[h * NN + j0 + (tid - 96)];

    #pragma unroll
    for (int p = 0; p < 4; p++) {
        int idx = tid + p * 128;
        int r = idx >> 4, f4 = (idx & 15) * 4;
        float4 v = *(const float4*)&d_gr[(i0 + r) * DD + h * FF + f4];
        *(float4*)&grs[r * 64 + f4] = v;
        float4 w = *(const float4*)&d_gl[(j0 + r) * DD + h * FF + f4];
        *(float2*)&gls[r * 66 + f4]     = make_float2(w.x, w.y);
        *(float2*)&gls[r * 66 + f4 + 2] = make_float2(w.z, w.w);
    }
    __syncthreads();

    int jj = tid & 31;
    int ib = tid >> 5;        // 0..3
    float acc[8] = {0,0,0,0,0,0,0,0};
    #pragma unroll 8
    for (int f = 0; f < 64; f += 2) {
        float2 gl2 = *(float2*)&gls[jj * 66 + f];
        float2 a2  = *(float2*)&as[f];
        #pragma unroll
        for (int q = 0; q < 8; q++) {
            float2 g2 = *(float2*)&grs[(ib + q * 4) * 64 + f];
            float v0 = g2.x + gl2.x;
            float v1 = g2.y + gl2.y;
            acc[q] = fmaf(a2.x, fabsf(v0), acc[q]);
            acc[q] = fmaf(a2.y, fabsf(v1), acc[q]);
        }
    }
    float lvj = lvs[jj];
    int j = j0 + jj;
    #pragma unroll
    for (int q = 0; q < 8; q++) {
        int i = i0 + ib + q * 4;
        float e = 0.6f * (rvs[ib + q * 4] + lvj) + 0.4f * acc[q];
        int m = adj[i * NN + j];
        d_E[(h * NN + i) * NN + j] = (m != 0 || i == j) ? e : -1e30f;
    }
}

// ============================================================
// Kernel 3: in-place softmax over j of E[h][i][:]. Grid (384, 8), 128 threads.
// ============================================================
__global__ __launch_bounds__(128) void softmax_kernel()
{
    int i = blockIdx.x, h = blockIdx.y;
    float* row = &d_E[(h * NN + i) * NN];
    int tid = threadIdx.x;

    float v[3];
    float m = -1e38f;
    #pragma unroll
    for (int p = 0; p < 3; p++) { v[p] = row[tid + p * 128]; m = fmaxf(m, v[p]); }
    #pragma unroll
    for (int o = 16; o > 0; o >>= 1) m = fmaxf(m, __shfl_xor_sync(0xffffffffu, m, o));
    __shared__ float sm[4];
    if ((tid & 31) == 0) sm[tid >> 5] = m;
    __syncthreads();
    float M = fmaxf(fmaxf(sm[0], sm[1]), fmaxf(sm[2], sm[3]));

    float s = 0.f;
    #pragma unroll
    for (int p = 0; p < 3; p++) { v[p] = expf(v[p] - M); s += v[p]; }
    #pragma unroll
    for (int o = 16; o > 0; o >>= 1) s += __shfl_xor_sync(0xffffffffu, s, o);
    __shared__ float ss[4];
    if ((tid & 31) == 0) ss[tid >> 5] = s;
    __syncthreads();
    float inv = 1.f / (ss[0] + ss[1] + ss[2] + ss[3]);
    #pragma unroll
    for (int p = 0; p < 3; p++) row[tid + p * 128] = v[p] * inv;
}

// ============================================================
// Kernel 4a: split-K aggregation partials, ONE 32-j tile per block.
// part[s][i, h*64+f] = sum_{j in tile s} att[h,i,j] * g_r[j, h*64+f]
// Grid (12 itiles, 8 heads, 12 jtiles), 128 threads, 4x4 micro-tile.
// ============================================================
__global__ __launch_bounds__(128) void aggregate_kernel()
{
    __shared__ float att_s[32 * 40];   // 16B-aligned rows, broadcast reads
    __shared__ float gr_s[32 * 64];

    int tid = threadIdx.x;
    int i0 = blockIdx.x * 32;
    int h  = blockIdx.y;
    int s  = blockIdx.z;
    int j0 = s * 32;

    int ib = tid >> 4;                 // 0..7
    int f  = (tid & 15) * 4;

    #pragma unroll
    for (int q = 0; q < 2; q++) {
        int idx = tid + q * 128;
        int ii = idx >> 3, jc = (idx & 7) * 4;
        float4 v = *(const float4*)&d_E[(h * NN + i0 + ii) * NN + j0 + jc];
        *(float4*)&att_s[ii * 40 + jc] = v;
    }
    #pragma unroll
    for (int p = 0; p < 4; p++) {
        int idx = tid + p * 128;
        int jj = idx >> 4, ff = (idx & 15) * 4;
        *(float4*)&gr_s[jj * 64 + ff] =
            *(const float4*)&d_gr[(j0 + jj) * DD + h * FF + ff];
    }
    __syncthreads();

    float acc[4][4] = {};
    #pragma unroll
    for (int jj = 0; jj < 32; jj++) {
        float4 g = *(float4*)&gr_s[jj * 64 + f];
        #pragma unroll
        for (int q = 0; q < 4; q++) {
            float av = att_s[(ib + q * 8) * 40 + jj];
            acc[q][0] = fmaf(av, g.x, acc[q][0]);
            acc[q][1] = fmaf(av, g.y, acc[q][1]);
            acc[q][2] = fmaf(av, g.z, acc[q][2]);
            acc[q][3] = fmaf(av, g.w, acc[q][3]);
        }
    }
    #pragma unroll
    for (int q = 0; q < 4; q++) {
        int i = i0 + ib + q * 8;
        *(float4*)&d_part[(s * NN + i) * DD + h * FF + f] =
            make_float4(acc[q][0], acc[q][1], acc[q][2], acc[q][3]);
    }
}

// ============================================================
// Kernel 4b: finalize. out = xin + act(sum_s part[s])
// Grid 192, 256 threads, float4 per thread.
// ============================================================
__global__ __launch_bounds__(256) void finalize_kernel(
    const float* __restrict__ xin_ext, int use_x1_in,
    float* __restrict__ out_ext, int write_x1, int do_elu)
{
    const float* xin  = use_x1_in ? d_x1 : xin_ext;
    float*       outp = write_x1  ? d_x1 : out_ext;

    int e = (blockIdx.x * 256 + threadIdx.x) * 4;
    float v0 = 0.f, v1 = 0.f, v2 = 0.f, v3 = 0.f;
    #pragma unroll
    for (int s = 0; s < SPL; s++) {
        float4 p = *(const float4*)&d_part[s * NN * DD + e];
        v0 += p.x; v1 += p.y; v2 += p.z; v3 += p.w;
    }
    float4 xv = *(const float4*)&xin[e];
    if (do_elu) {
        v0 = v0 > 0.f ? v0 : expm1f(v0);
        v1 = v1 > 0.f ? v1 : expm1f(v1);
        v2 = v2 > 0.f ? v2 : expm1f(v2);
        v3 = v3 > 0.f ? v3 : expm1f(v3);
    }
    *(float4*)&outp[e] = make_float4(xv.x + v0, xv.y + v1, xv.z + v2, xv.w + v3);
}

// ============================================================
extern "C" void kernel_launch(void* const* d_in, const int* in_sizes, int n_in,
                              void* d_out, int out_size)
{
    const float* x   = (const float*)d_in[0];
    const int*   adj = (const int*)  d_in[1];
    const float* Wl0 = (const float*)d_in[2];
    const float* Wr0 = (const float*)d_in[3];
    const float* a0  = (const float*)d_in[4];
    const float* Wl1 = (const float*)d_in[5];
    const float* Wr1 = (const float*)d_in[6];
    const float* a1  = (const float*)d_in[7];
    float* out = (float*)d_out;

    dim3 gg(16, 12);            // gemm: 192 blocks
    dim3 glg(12, 12, 8);        // logits: 1152 blocks
    dim3 gs(384, 8);            // softmax
    dim3 ga(12, 8, SPL);        // aggregate partials: 1152 blocks
    int  gf = (NN * DD) / (256 * 4);   // finalize: 192 blocks

    // ---- layer 0 ----
    gemm_kernel<<<gg, 128>>>(x, 0, Wl0, Wr0, a0);
    logits_kernel<<<glg, 128>>>(a0, adj);
    softmax_kernel<<<gs, 128>>>();
    aggregate_kernel<<<ga, 128>>>();
    finalize_kernel<<<gf, 256>>>(x, 0, nullptr, /*write_x1=*/1, /*elu=*/1);

    // ---- layer 1 ----
    gemm_kernel<<<gg, 128>>>(nullptr, 1, Wl1, Wr1, a1);
    logits_kernel<<<glg, 128>>>(a1, adj);
    softmax_kernel<<<gs, 128>>>();
    aggregate_kernel<<<ga, 128>>>();
    finalize_kernel<<<gf, 256>>>(nullptr, 1, out, /*write_x1=*/0, /*elu=*/0);
}

// round 10
// speedup vs baseline: 1.9929x; 1.0094x over previous
#include <cuda_runtime.h>
#include <math.h>
#include <stdint.h>

#define NN 384
#define DD 512
#define HH 8
#define FF 64
#define SPL 12

typedef unsigned long long ull;

// ---- scratch (no allocations allowed) ----
__device__ float d_gl[NN * DD];
__device__ float d_gr[NN * DD];
__device__ float d_x1[NN * DD];
__device__ float d_rvec[HH * NN];   // r[h,i] = sum_f a_f * gr[i,h,f]
__device__ float d_lvec[HH * NN];   // l[h,j] = sum_f a_f * gl[j,h,f]
__device__ float d_part[SPL * NN * DD];
__device__ float d_pm[SPL * HH * NN];   // per-split row max
__device__ float d_ps[SPL * HH * NN];   // per-split row sum of exp

// ---- tf32 helpers ----
__device__ __forceinline__ uint32_t f2tf32(float x) {
    uint32_t r;
    asm("cvt.rna.tf32.f32 %0, %1;" : "=r"(r) : "f"(x));
    return r;
}
__device__ __forceinline__ void mma_tf32(float c[4], const uint32_t a[4],
                                         uint32_t b0, uint32_t b1) {
    asm volatile(
        "mma.sync.aligned.m16n8k8.row.col.f32.tf32.tf32.f32 "
        "{%0,%1,%2,%3}, {%4,%5,%6,%7}, {%8,%9}, {%0,%1,%2,%3};\n"
        : "+f"(c[0]), "+f"(c[1]), "+f"(c[2]), "+f"(c[3])
        : "r"(a[0]), "r"(a[1]), "r"(a[2]), "r"(a[3]), "r"(b0), "r"(b1));
}

// ---- packed f32x2 helpers (Blackwell FFMA2 path) ----
__device__ __forceinline__ ull f2add(ull a, ull b) {
    ull r; asm("add.rn.f32x2 %0, %1, %2;" : "=l"(r) : "l"(a), "l"(b)); return r;
}
__device__ __forceinline__ ull f2fma(ull a, ull b, ull c) {
    ull r; asm("fma.rn.f32x2 %0, %1, %2, %3;" : "=l"(r) : "l"(a), "l"(b), "l"(c)); return r;
}
__device__ __forceinline__ ull f2pack(float lo, float hi) {
    ull r; asm("mov.b64 %0, {%1, %2};" : "=l"(r) : "r"(__float_as_uint(lo)), "r"(__float_as_uint(hi)));
    return r;
}
__device__ __forceinline__ float f2lo(ull v) { return __uint_as_float((unsigned)(v & 0xFFFFFFFFu)); }
__device__ __forceinline__ float f2hi(ull v) { return __uint_as_float((unsigned)(v >> 32)); }

// ============================================================
// Kernel 1: g_l = xin @ W_l, g_r = xin @ W_r via tf32x3 mma.sync.
// Block: 128 thr (4 warps, 2M x 2N), BM=32, BN=64, BK=32 stages, pipelined.
// Grid (16, 12): bx<8 -> W_l head bx, bx>=8 -> W_r head bx-8. 192 blocks.
// Epilogue: fused rank-1 projections r/l = sum_f a_f * g[:,h,f] (fp32).
// ============================================================
__global__ __launch_bounds__(128) void gemm_kernel(
    const float* __restrict__ xin_ext, int use_x1,
    const float* __restrict__ Wl, const float* __restrict__ Wr,
    const float* __restrict__ a_vec)
{
    const float* xin = use_x1 ? d_x1 : xin_ext;
    __shared__ float As[32][36];
    __shared__ float Bs[32][68];
    __shared__ float red[2][32];

    int tid  = threadIdx.x;
    int bx   = blockIdx.x;
    int i0   = blockIdx.y * 32;
    int isL  = (bx < 8);
    int c0   = (bx & 7) * 64;
    const float* W    = isL ? Wl : Wr;
    float*       outp = isL ? d_gl : d_gr;

    int warp  = tid >> 5;
    int lane  = tid & 31;
    int g     = lane >> 2;
    int tig   = lane & 3;
    int m0    = (warp & 1) * 16;
    int n0    = (warp >> 1) * 32;

    int aRow0 = tid >> 3,            aCol = (tid & 7) * 4;
    int bRow0 = tid >> 4,            bCol = (tid & 15) * 4;

    float c[4][4] = {};

    float4 ra0, ra1, rb0, rb1, rb2, rb3;
    ra0 = *(const float4*)&xin[(i0 + aRow0)      * DD + aCol];
    ra1 = *(const float4*)&xin[(i0 + aRow0 + 16) * DD + aCol];
    rb0 = *(const float4*)&W[(bRow0)      * DD + c0 + bCol];
    rb1 = *(const float4*)&W[(bRow0 +  8) * DD + c0 + bCol];
    rb2 = *(const float4*)&W[(bRow0 + 16) * DD + c0 + bCol];
    rb3 = *(const float4*)&W[(bRow0 + 24) * DD + c0 + bCol];

    for (int k0 = 0; k0 < DD; k0 += 32) {
        *(float4*)&As[aRow0][aCol]      = ra0;
        *(float4*)&As[aRow0 + 16][aCol] = ra1;
        *(float4*)&Bs[bRow0][bCol]      = rb0;
        *(float4*)&Bs[bRow0 +  8][bCol] = rb1;
        *(float4*)&Bs[bRow0 + 16][bCol] = rb2;
        *(float4*)&Bs[bRow0 + 24][bCol] = rb3;
        __syncthreads();

        int kn = k0 + 32;
        if (kn < DD) {
            ra0 = *(const float4*)&xin[(i0 + aRow0)      * DD + kn + aCol];
            ra1 = *(const float4*)&xin[(i0 + aRow0 + 16) * DD + kn + aCol];
            rb0 = *(const float4*)&W[(kn + bRow0)      * DD + c0 + bCol];
            rb1 = *(const float4*)&W[(kn + bRow0 +  8) * DD + c0 + bCol];
            rb2 = *(const float4*)&W[(kn + bRow0 + 16) * DD + c0 + bCol];
            rb3 = *(const float4*)&W[(kn + bRow0 + 24) * DD + c0 + bCol];
        }

        #pragma unroll
        for (int kc = 0; kc < 4; kc++) {
            int kb = kc * 8;
            float av[4];
            av[0] = As[m0 + g][kb + tig];
            av[1] = As[m0 + g + 8][kb + tig];
            av[2] = As[m0 + g][kb + tig + 4];
            av[3] = As[m0 + g + 8][kb + tig + 4];
            uint32_t ah[4], al[4];
            #pragma unroll
            for (int e = 0; e < 4; e++) {
                ah[e] = f2tf32(av[e]);
                al[e] = f2tf32(av[e] - __uint_as_float(ah[e]));
            }
            #pragma unroll
            for (int t = 0; t < 4; t++) {
                float b0f = Bs[kb + tig][n0 + t * 8 + g];
                float b1f = Bs[kb + tig + 4][n0 + t * 8 + g];
                uint32_t bh0 = f2tf32(b0f), bh1 = f2tf32(b1f);
                uint32_t bl0 = f2tf32(b0f - __uint_as_float(bh0));
                uint32_t bl1 = f2tf32(b1f - __uint_as_float(bh1));
                mma_tf32(c[t], ah, bh0, bh1);   // hi*hi
                mma_tf32(c[t], al, bh0, bh1);   // lo*hi
                mma_tf32(c[t], ah, bl0, bl1);   // hi*lo
            }
        }
        __syncthreads();
    }

    int r0 = i0 + m0 + g;
    int r1 = r0 + 8;
    #pragma unroll
    for (int t = 0; t < 4; t++) {
        int cc = c0 + n0 + t * 8 + 2 * tig;
        *(float2*)&outp[r0 * DD + cc] = make_float2(c[t][0], c[t][1]);
        *(float2*)&outp[r1 * DD + cc] = make_float2(c[t][2], c[t][3]);
    }

    float p0 = 0.f, p1 = 0.f;
    #pragma unroll
    for (int t = 0; t < 4; t++) {
        int fc = n0 + t * 8 + 2 * tig;
        float av0 = a_vec[fc], av1 = a_vec[fc + 1];
        p0 = fmaf(av0, c[t][0], fmaf(av1, c[t][1], p0));
        p1 = fmaf(av0, c[t][2], fmaf(av1, c[t][3], p1));
    }
    p0 += __shfl_xor_sync(0xffffffffu, p0, 1);
    p0 += __shfl_xor_sync(0xffffffffu, p0, 2);
    p1 += __shfl_xor_sync(0xffffffffu, p1, 1);
    p1 += __shfl_xor_sync(0xffffffffu, p1, 2);
    if (tig == 0) {
        red[warp >> 1][m0 + g]     = p0;
        red[warp >> 1][m0 + 8 + g] = p1;
    }
    __syncthreads();
    if (tid < 32) {
        int h = bx & 7;
        float* dst = isL ? d_lvec : d_rvec;
        dst[h * NN + i0 + tid] = red[0][tid] + red[1][tid];
    }
}

// ============================================================
// Kernel 2: FUSED attention: logits + per-split online softmax + aggregation.
// Block = (32 i-rows, head h, 32-j split s). Grid (12, 8, 12) = 1152 blocks.
// Phase 1: e[i][j] = 0.6*(r_i+l_j) + 0.4*sum_f a_f*|gr_i,f + gl_j,f|  (f32x2 packed)
// Phase 2: per-row max m, exp in place, sum s  -> d_pm/d_ps
// Phase 3: P[i,f] = sum_j exp(e-m)*gr_j,f      (f32x2 packed) -> d_part
// ============================================================
__global__ __launch_bounds__(128) void attn_kernel(
    const float* __restrict__ a_vec, const int* __restrict__ adj)
{
    __shared__ __align__(16) float gri[32 * 64];
    __shared__ __align__(16) float glj[32 * 66];
    __shared__ __align__(16) float grj[32 * 64];
    __shared__ __align__(16) float ew[32 * 33];
    __shared__ __align__(16) float as[64];
    __shared__ float rvs[32], lvs[32];
    __shared__ float redm[4][32], reds[4][32];

    int tid = threadIdx.x;
    int i0 = blockIdx.x * 32;
    int h  = blockIdx.y;
    int s  = blockIdx.z;
    int j0 = s * 32;

    if (tid < 64)       as[tid]       = a_vec[tid];
    else if (tid < 96)  rvs[tid - 64] = d_rvec[h * NN + i0 + (tid - 64)];
    else                lvs[tid - 96] = d_lvec[h * NN + j0 + (tid - 96)];

    #pragma unroll
    for (int p = 0; p < 4; p++) {
        int idx = tid + p * 128;
        int r = idx >> 4, f4 = (idx & 15) * 4;
        *(float4*)&gri[r * 64 + f4] = *(const float4*)&d_gr[(i0 + r) * DD + h * FF + f4];
        *(float4*)&grj[r * 64 + f4] = *(const float4*)&d_gr[(j0 + r) * DD + h * FF + f4];
        float4 w = *(const float4*)&d_gl[(j0 + r) * DD + h * FF + f4];
        *(float2*)&glj[r * 66 + f4]     = make_float2(w.x, w.y);
        *(float2*)&glj[r * 66 + f4 + 2] = make_float2(w.z, w.w);
    }

    int jj = tid & 31;
    int ib = tid >> 5;                 // 0..3
    int mk[8];
    #pragma unroll
    for (int q = 0; q < 8; q++) {      // hoisted mask loads (overlap with smem fill)
        int i = i0 + ib + q * 4;
        mk[q] = (adj[i * NN + j0 + jj] != 0) || (i == j0 + jj);
    }
    __syncthreads();

    // ---- phase 1: logits (packed f32x2) ----
    ull accp[8] = {0,0,0,0,0,0,0,0};
    #pragma unroll 8
    for (int f = 0; f < 64; f += 2) {
        ull gl2 = *(const ull*)&glj[jj * 66 + f];
        ull a2  = *(const ull*)&as[f];
        #pragma unroll
        for (int q = 0; q < 8; q++) {
            ull v = f2add(*(const ull*)&gri[(ib + q * 4) * 64 + f], gl2);
            v &= 0x7FFFFFFF7FFFFFFFULL;              // packed fabs
            accp[q] = f2fma(a2, v, accp[q]);
        }
    }
    float lvj = lvs[jj];
    #pragma unroll
    for (int q = 0; q < 8; q++) {
        int il = ib + q * 4;
        float sum = f2lo(accp[q]) + f2hi(accp[q]);
        float e = 0.6f * (rvs[il] + lvj) + 0.4f * sum;
        ew[il * 33 + jj] = mk[q] ? e : -1e30f;
    }
    __syncthreads();

    // ---- phase 2: per-row stats + exp in place ----
    int r  = tid & 31;
    int qd = tid >> 5;
    float pm = -1e38f;
    #pragma unroll
    for (int jn = 0; jn < 8; jn++) pm = fmaxf(pm, ew[r * 33 + qd * 8 + jn]);
    redm[qd][r] = pm;
    __syncthreads();
    float M = fmaxf(fmaxf(redm[0][r], redm[1][r]), fmaxf(redm[2][r], redm[3][r]));
    float ssum = 0.f;
    #pragma unroll
    for (int jn = 0; jn < 8; jn++) {
        int ix = r * 33 + qd * 8 + jn;
        float w = __expf(ew[ix] - M);
        ew[ix] = w;
        ssum += w;
    }
    reds[qd][r] = ssum;
    __syncthreads();
    if (qd == 0) {
        d_pm[(s * HH + h) * NN + i0 + r] = M;
        d_ps[(s * HH + h) * NN + i0 + r] = reds[0][r] + reds[1][r] + reds[2][r] + reds[3][r];
    }

    // ---- phase 3: aggregation (packed f32x2) ----
    int ib2 = tid >> 4;                // 0..7
    int f   = (tid & 15) * 4;
    ull acc0[4] = {0,0,0,0}, acc1[4] = {0,0,0,0};
    #pragma unroll
    for (int j2 = 0; j2 < 32; j2++) {
        ull g01 = *(const ull*)&grj[j2 * 64 + f];
        ull g23 = *(const ull*)&grj[j2 * 64 + f + 2];
        #pragma unroll
        for (int q = 0; q < 4; q++) {
            float w = ew[(ib2 + q * 8) * 33 + j2];
            ull ww = f2pack(w, w);
            acc0[q] = f2fma(ww, g01, acc0[q]);
            acc1[q] = f2fma(ww, g23, acc1[q]);
        }
    }
    #pragma unroll
    for (int q = 0; q < 4; q++) {
        int i = i0 + ib2 + q * 8;
        *(float4*)&d_part[(s * NN + i) * DD + h * FF + f] =
            make_float4(f2lo(acc0[q]), f2hi(acc0[q]), f2lo(acc1[q]), f2hi(acc1[q]));
    }
}

// ============================================================
// Kernel 3: finalize. Combine per-split partials with global softmax
// normalization, then residual + optional ELU.
// out[i, h*64+f] = xin + act( sum_s P_s*exp(m_s-M) / sum_s s_s*exp(m_s-M) )
// Grid (12, 8), 256 threads.
// ============================================================
__global__ __launch_bounds__(256) void finalize_kernel(
    const float* __restrict__ xin_ext, int use_x1_in,
    float* __restrict__ out_ext, int write_x1, int do_elu)
{
    const float* xin  = use_x1_in ? d_x1 : xin_ext;
    float*       outp = write_x1  ? d_x1 : out_ext;
    __shared__ float coef[32][SPL + 1];

    int tid = threadIdx.x;
    int i0 = blockIdx.x * 32;
    int h  = blockIdx.y;

    if (tid < 32) {
        int r = tid;
        float m[SPL], c[SPL];
        float M = -1e38f;
        #pragma unroll
        for (int s2 = 0; s2 < SPL; s2++) {
            m[s2] = d_pm[(s2 * HH + h) * NN + i0 + r];
            M = fmaxf(M, m[s2]);
        }
        float D = 0.f;
        #pragma unroll
        for (int s2 = 0; s2 < SPL; s2++) {
            c[s2] = __expf(m[s2] - M);
            D += d_ps[(s2 * HH + h) * NN + i0 + r] * c[s2];
        }
        float invD = 1.f / D;
        #pragma unroll
        for (int s2 = 0; s2 < SPL; s2++) coef[r][s2] = c[s2] * invD;
    }
    __syncthreads();

    int il = tid >> 3;
    int f8 = (tid & 7) * 8;
    int i  = i0 + il;
    int base = i * DD + h * FF + f8;

    float4 A = {0,0,0,0}, B = {0,0,0,0};
    #pragma unroll
    for (int s2 = 0; s2 < SPL; s2++) {
        float cc = coef[il][s2];
        const float* pp = &d_part[(s2 * NN + i) * DD + h * FF + f8];
        float4 p = *(const float4*)pp;
        float4 q = *(const float4*)(pp + 4);
        A.x = fmaf(cc, p.x, A.x); A.y = fmaf(cc, p.y, A.y);
        A.z = fmaf(cc, p.z, A.z); A.w = fmaf(cc, p.w, A.w);
        B.x = fmaf(cc, q.x, B.x); B.y = fmaf(cc, q.y, B.y);
        B.z = fmaf(cc, q.z, B.z); B.w = fmaf(cc, q.w, B.w);
    }
    if (do_elu) {
        A.x = A.x > 0.f ? A.x : expm1f(A.x);
        A.y = A.y > 0.f ? A.y : expm1f(A.y);
        A.z = A.z > 0.f ? A.z : expm1f(A.z);
        A.w = A.w > 0.f ? A.w : expm1f(A.w);
        B.x = B.x > 0.f ? B.x : expm1f(B.x);
        B.y = B.y > 0.f ? B.y : expm1f(B.y);
        B.z = B.z > 0.f ? B.z : expm1f(B.z);
        B.w = B.w > 0.f ? B.w : expm1f(B.w);
    }
    float4 xa = *(const float4*)&xin[base];
    float4 xb = *(const float4*)&xin[base + 4];
    *(float4*)&outp[base]     = make_float4(xa.x + A.x, xa.y + A.y, xa.z + A.z, xa.w + A.w);
    *(float4*)&outp[base + 4] = make_float4(xb.x + B.x, xb.y + B.y, xb.z + B.z, xb.w + B.w);
}

// ============================================================
extern "C" void kernel_launch(void* const* d_in, const int* in_sizes, int n_in,
                              void* d_out, int out_size)
{
    const float* x   = (const float*)d_in[0];
    const int*   adj = (const int*)  d_in[1];
    const float* Wl0 = (const float*)d_in[2];
    const float* Wr0 = (const float*)d_in[3];
    const float* a0  = (const float*)d_in[4];
    const float* Wl1 = (const float*)d_in[5];
    const float* Wr1 = (const float*)d_in[6];
    const float* a1  = (const float*)d_in[7];
    float* out = (float*)d_out;

    dim3 gg(16, 12);            // gemm: 192 blocks
    dim3 gat(12, 8, SPL);       // fused attention: 1152 blocks
    dim3 gf(12, 8);             // finalize: 96 blocks

    // ---- layer 0 ----
    gemm_kernel<<<gg, 128>>>(x, 0, Wl0, Wr0, a0);
    attn_kernel<<<gat, 128>>>(a0, adj);
    finalize_kernel<<<gf, 256>>>(x, 0, nullptr, /*write_x1=*/1, /*elu=*/1);

    // ---- layer 1 ----
    gemm_kernel<<<gg, 128>>>(nullptr, 1, Wl1, Wr1, a1);
    attn_kernel<<<gat, 128>>>(a1, adj);
    finalize_kernel<<<gf, 256>>>(nullptr, 1, out, /*write_x1=*/0, /*elu=*/0);
}

// round 13
// speedup vs baseline: 2.4225x; 1.2156x over previous
#include <cuda_runtime.h>
#include <cuda_bf16.h>
#include <math.h>
#include <stdint.h>

#define NN 384
#define DD 512
#define HH 8
#define FF 64
#define SPL 12

typedef unsigned long long ull;

// ---- scratch (no allocations allowed) ----
__device__ float d_gl[NN * DD];
__device__ float d_gr[NN * DD];
__device__ float d_x1[NN * DD];
__device__ float d_rvec[HH * NN];
__device__ float d_lvec[HH * NN];
__device__ float d_part[SPL * NN * DD];
__device__ float d_pm[SPL * HH * NN];
__device__ float d_ps[SPL * HH * NN];
// bf16 hi/lo operand storage
__device__ __nv_bfloat16 d_wbh[4 * DD * DD];
__device__ __nv_bfloat16 d_wbl[4 * DD * DD];
__device__ __nv_bfloat16 d_xbh[2 * NN * DD];
__device__ __nv_bfloat16 d_xbl[2 * NN * DD];

// ---- packed f32x2 helpers ----
__device__ __forceinline__ ull f2add(ull a, ull b) {
    ull r; asm("add.rn.f32x2 %0, %1, %2;" : "=l"(r) : "l"(a), "l"(b)); return r;
}
__device__ __forceinline__ ull f2fma(ull a, ull b, ull c) {
    ull r; asm("fma.rn.f32x2 %0, %1, %2, %3;" : "=l"(r) : "l"(a), "l"(b), "l"(c)); return r;
}
__device__ __forceinline__ ull f2pack(float lo, float hi) {
    ull r; asm("mov.b64 %0, {%1, %2};" : "=l"(r) : "r"(__float_as_uint(lo)), "r"(__float_as_uint(hi)));
    return r;
}
__device__ __forceinline__ float f2lo(ull v) { return __uint_as_float((unsigned)(v & 0xFFFFFFFFu)); }
__device__ __forceinline__ float f2hi(ull v) { return __uint_as_float((unsigned)(v >> 32)); }

__device__ __forceinline__ uint32_t smem_u32(const void* p) {
    uint32_t a;
    asm("{ .reg .u64 t; cvta.to.shared.u64 t, %1; cvt.u32.u64 %0, t; }" : "=r"(a) : "l"(p));
    return a;
}
__device__ __forceinline__ void ldsm4(uint32_t r[4], uint32_t addr) {
    asm volatile("ldmatrix.sync.aligned.m8n8.x4.shared.b16 {%0,%1,%2,%3}, [%4];"
                 : "=r"(r[0]), "=r"(r[1]), "=r"(r[2]), "=r"(r[3]) : "r"(addr));
}
__device__ __forceinline__ void ldsm4t(uint32_t r[4], uint32_t addr) {
    asm volatile("ldmatrix.sync.aligned.m8n8.x4.trans.shared.b16 {%0,%1,%2,%3}, [%4];"
                 : "=r"(r[0]), "=r"(r[1]), "=r"(r[2]), "=r"(r[3]) : "r"(addr));
}
__device__ __forceinline__ void mma16816(float c[4], const uint32_t a[4],
                                         uint32_t b0, uint32_t b1) {
    asm volatile(
        "mma.sync.aligned.m16n8k16.row.col.f32.bf16.bf16.f32 "
        "{%0,%1,%2,%3}, {%4,%5,%6,%7}, {%8,%9}, {%0,%1,%2,%3};\n"
        : "+f"(c[0]), "+f"(c[1]), "+f"(c[2]), "+f"(c[3])
        : "r"(a[0]), "r"(a[1]), "r"(a[2]), "r"(a[3]), "r"(b0), "r"(b1));
}

// ============================================================
// Kernel 0: one-time fp32 -> bf16 hi/lo conversion of W (x4) and x.
// Grid (256, 5): by 0..3 = W matrices, by 4 = x (192 active blocks).
// ============================================================
__global__ __launch_bounds__(256) void convert_kernel(
    const float* __restrict__ x,
    const float* __restrict__ Wl0, const float* __restrict__ Wr0,
    const float* __restrict__ Wl1, const float* __restrict__ Wr1)
{
    int by = blockIdx.y;
    const float* src;
    __nv_bfloat16 *dh, *dl;
    int limit;
    if (by < 4) {
        src = (by == 0) ? Wl0 : (by == 1) ? Wr0 : (by == 2) ? Wl1 : Wr1;
        dh = d_wbh + by * DD * DD; dl = d_wbl + by * DD * DD; limit = DD * DD;
    } else {
        src = x; dh = d_xbh; dl = d_xbl; limit = NN * DD;
    }
    int e = (blockIdx.x * 256 + threadIdx.x) * 4;
    if (e >= limit) return;
    float4 v = *(const float4*)&src[e];
    __nv_bfloat162 h0, h1, l0, l1;
    h0.x = __float2bfloat16(v.x); h0.y = __float2bfloat16(v.y);
    h1.x = __float2bfloat16(v.z); h1.y = __float2bfloat16(v.w);
    l0.x = __float2bfloat16(v.x - __bfloat162float(h0.x));
    l0.y = __float2bfloat16(v.y - __bfloat162float(h0.y));
    l1.x = __float2bfloat16(v.z - __bfloat162float(h1.x));
    l1.y = __float2bfloat16(v.w - __bfloat162float(h1.y));
    *(__nv_bfloat162*)&dh[e]     = h0;
    *(__nv_bfloat162*)&dh[e + 2] = h1;
    *(__nv_bfloat162*)&dl[e]     = l0;
    *(__nv_bfloat162*)&dl[e + 2] = l1;
}

// ============================================================
// Kernel 1: bf16x3 tensor-core GEMM. g = A @ W, A = x (bf16 hi/lo), W bf16 hi/lo.
// BM=32, BN=64, BK=64. 256 thr = 8 warps (2m x 4n), warp tile m16n16.
// Grid (16, 12): bx<8 -> W_l (head bx), else W_r (head bx-8). 192 blocks.
// C = Ah*Bh + Al*Bh + Ah*Bl, fp32 accum. Fused rank-1 r/l epilogue.
// ============================================================
__global__ __launch_bounds__(256) void gemm_kernel(int layer, const float* __restrict__ a_vec)
{
    __shared__ __align__(16) __nv_bfloat16 Ah[32][72], Al[32][72];
    __shared__ __align__(16) __nv_bfloat16 Bh[64][72], Bl[64][72];
    __shared__ float red[4][33];

    int tid = threadIdx.x;
    int bx  = blockIdx.x;
    int i0  = blockIdx.y * 32;
    int isL = (bx < 8);
    int c0  = (bx & 7) * 64;
    int widx = layer * 2 + (isL ? 0 : 1);
    const __nv_bfloat16* A_h = d_xbh + layer * NN * DD;
    const __nv_bfloat16* A_l = d_xbl + layer * NN * DD;
    const __nv_bfloat16* W_h = d_wbh + widx * DD * DD;
    const __nv_bfloat16* W_l = d_wbl + widx * DD * DD;
    float* outp = isL ? d_gl : d_gr;

    int warp = tid >> 5, lane = tid & 31;
    int wm = warp >> 2, wn = warp & 3;

    // staging coords (halves)
    int ar = tid >> 3, ac = (tid & 7) * 8;     // A: 1 granule/thread/buffer
    int br = tid >> 2, bc = (tid & 3) * 16;    // B: 2 granules/thread/buffer

    // ldmatrix base addresses
    uint32_t aadr_h = smem_u32(&Ah[wm * 16 + (lane & 15)][(lane >> 4) * 8]);
    uint32_t aadr_l = smem_u32(&Al[wm * 16 + (lane & 15)][(lane >> 4) * 8]);
    int bkrow = (lane & 7) + ((lane >> 3) & 1) * 8;
    uint32_t badr_h = smem_u32(&Bh[bkrow][wn * 16 + (lane >> 4) * 8]);
    uint32_t badr_l = smem_u32(&Bl[bkrow][wn * 16 + (lane >> 4) * 8]);

    float c0f[4] = {0,0,0,0};   // n-tile 0 (cols wn*16+0..7)
    float c1f[4] = {0,0,0,0};   // n-tile 1 (cols wn*16+8..15)

    uint4 pah, pal, pbh0, pbh1, pbl0, pbl1;
    pah  = *(const uint4*)&A_h[(i0 + ar) * DD + ac];
    pal  = *(const uint4*)&A_l[(i0 + ar) * DD + ac];
    pbh0 = *(const uint4*)&W_h[br * DD + c0 + bc];
    pbh1 = *(const uint4*)&W_h[br * DD + c0 + bc + 8];
    pbl0 = *(const uint4*)&W_l[br * DD + c0 + bc];
    pbl1 = *(const uint4*)&W_l[br * DD + c0 + bc + 8];

    for (int k0 = 0; k0 < DD; k0 += 64) {
        *(uint4*)&Ah[ar][ac]      = pah;
        *(uint4*)&Al[ar][ac]      = pal;
        *(uint4*)&Bh[br][bc]      = pbh0;
        *(uint4*)&Bh[br][bc + 8]  = pbh1;
        *(uint4*)&Bl[br][bc]      = pbl0;
        *(uint4*)&Bl[br][bc + 8]  = pbl1;
        __syncthreads();

        int kn = k0 + 64;
        if (kn < DD) {
            pah  = *(const uint4*)&A_h[(i0 + ar) * DD + kn + ac];
            pal  = *(const uint4*)&A_l[(i0 + ar) * DD + kn + ac];
            pbh0 = *(const uint4*)&W_h[(kn + br) * DD + c0 + bc];
            pbh1 = *(const uint4*)&W_h[(kn + br) * DD + c0 + bc + 8];
            pbl0 = *(const uint4*)&W_l[(kn + br) * DD + c0 + bc];
            pbl1 = *(const uint4*)&W_l[(kn + br) * DD + c0 + bc + 8];
        }

        #pragma unroll
        for (int kc = 0; kc < 4; kc++) {
            uint32_t ah[4], al[4], bh[4], bl[4];
            ldsm4 (ah, aadr_h + kc * 32);          // +16 halves in k
            ldsm4 (al, aadr_l + kc * 32);
            ldsm4t(bh, badr_h + kc * 16 * 144);    // +16 k-rows (144B row stride)
            ldsm4t(bl, badr_l + kc * 16 * 144);
            mma16816(c0f, ah, bh[0], bh[1]);
            mma16816(c0f, al, bh[0], bh[1]);
            mma16816(c0f, ah, bl[0], bl[1]);
            mma16816(c1f, ah, bh[2], bh[3]);
            mma16816(c1f, al, bh[2], bh[3]);
            mma16816(c1f, ah, bl[2], bl[3]);
        }
        __syncthreads();
    }

    // ---- store g (fp32) ----
    int r0 = i0 + wm * 16 + (lane >> 2);
    int r1 = r0 + 8;
    int cb = c0 + wn * 16 + 2 * (lane & 3);
    *(float2*)&outp[r0 * DD + cb]     = make_float2(c0f[0], c0f[1]);
    *(float2*)&outp[r0 * DD + cb + 8] = make_float2(c1f[0], c1f[1]);
    *(float2*)&outp[r1 * DD + cb]     = make_float2(c0f[2], c0f[3]);
    *(float2*)&outp[r1 * DD + cb + 8] = make_float2(c1f[2], c1f[3]);

    // ---- fused rank-1 projection (head = bx&7) ----
    int f0 = wn * 16 + 2 * (lane & 3);
    float af0 = a_vec[f0], af1 = a_vec[f0 + 1];
    float af8 = a_vec[f0 + 8], af9 = a_vec[f0 + 9];
    float p0 = af0 * c0f[0] + af1 * c0f[1] + af8 * c1f[0] + af9 * c1f[1];
    float p1 = af0 * c0f[2] + af1 * c0f[3] + af8 * c1f[2] + af9 * c1f[3];
    p0 += __shfl_xor_sync(0xffffffffu, p0, 1);
    p0 += __shfl_xor_sync(0xffffffffu, p0, 2);
    p1 += __shfl_xor_sync(0xffffffffu, p1, 1);
    p1 += __shfl_xor_sync(0xffffffffu, p1, 2);
    if ((lane & 3) == 0) {
        red[wn][wm * 16 + (lane >> 2)]     = p0;
        red[wn][wm * 16 + 8 + (lane >> 2)] = p1;
    }
    __syncthreads();
    if (tid < 32) {
        int h = bx & 7;
        float* dst = isL ? d_lvec : d_rvec;
        dst[h * NN + i0 + tid] = red[0][tid] + red[1][tid] + red[2][tid] + red[3][tid];
    }
}

// ============================================================
// Kernel 2: FUSED attention: logits + per-split softmax + aggregation.
// Block = (32 i-rows, head h, 32-j split s). Grid (12, 8, 12) = 1152 blocks.
// ============================================================
__global__ __launch_bounds__(128) void attn_kernel(
    const float* __restrict__ a_vec, const int* __restrict__ adj)
{
    __shared__ __align__(16) float gri[32 * 64];
    __shared__ __align__(16) float glj[32 * 66];
    __shared__ __align__(16) float grj[32 * 64];
    __shared__ __align__(16) float ew[32 * 33];
    __shared__ __align__(16) float as[64];
    __shared__ float rvs[32], lvs[32];
    __shared__ float redm[4][32], reds[4][32];

    int tid = threadIdx.x;
    int i0 = blockIdx.x * 32;
    int h  = blockIdx.y;
    int s  = blockIdx.z;
    int j0 = s * 32;

    if (tid < 64)       as[tid]       = a_vec[tid];
    else if (tid < 96)  rvs[tid - 64] = d_rvec[h * NN + i0 + (tid - 64)];
    else                lvs[tid - 96] = d_lvec[h * NN + j0 + (tid - 96)];

    #pragma unroll
    for (int p = 0; p < 4; p++) {
        int idx = tid + p * 128;
        int r = idx >> 4, f4 = (idx & 15) * 4;
        *(float4*)&gri[r * 64 + f4] = *(const float4*)&d_gr[(i0 + r) * DD + h * FF + f4];
        *(float4*)&grj[r * 64 + f4] = *(const float4*)&d_gr[(j0 + r) * DD + h * FF + f4];
        float4 w = *(const float4*)&d_gl[(j0 + r) * DD + h * FF + f4];
        *(float2*)&glj[r * 66 + f4]     = make_float2(w.x, w.y);
        *(float2*)&glj[r * 66 + f4 + 2] = make_float2(w.z, w.w);
    }

    int jj = tid & 31;
    int ib = tid >> 5;
    int mk[8];
    #pragma unroll
    for (int q = 0; q < 8; q++) {
        int i = i0 + ib + q * 4;
        mk[q] = (adj[i * NN + j0 + jj] != 0) || (i == j0 + jj);
    }
    __syncthreads();

    // ---- phase 1: logits (packed f32x2) ----
    ull accp[8] = {0,0,0,0,0,0,0,0};
    #pragma unroll 8
    for (int f = 0; f < 64; f += 2) {
        ull gl2 = *(const ull*)&glj[jj * 66 + f];
        ull a2  = *(const ull*)&as[f];
        #pragma unroll
        for (int q = 0; q < 8; q++) {
            ull v = f2add(*(const ull*)&gri[(ib + q * 4) * 64 + f], gl2);
            v &= 0x7FFFFFFF7FFFFFFFULL;
            accp[q] = f2fma(a2, v, accp[q]);
        }
    }
    float lvj = lvs[jj];
    #pragma unroll
    for (int q = 0; q < 8; q++) {
        int il = ib + q * 4;
        float sum = f2lo(accp[q]) + f2hi(accp[q]);
        float e = 0.6f * (rvs[il] + lvj) + 0.4f * sum;
        ew[il * 33 + jj] = mk[q] ? e : -1e30f;
    }
    __syncthreads();

    // ---- phase 2: per-row stats + exp in place ----
    int r  = tid & 31;
    int qd = tid >> 5;
    float pm = -1e38f;
    #pragma unroll
    for (int jn = 0; jn < 8; jn++) pm = fmaxf(pm, ew[r * 33 + qd * 8 + jn]);
    redm[qd][r] = pm;
    __syncthreads();
    float M = fmaxf(fmaxf(redm[0][r], redm[1][r]), fmaxf(redm[2][r], redm[3][r]));
    float ssum = 0.f;
    #pragma unroll
    for (int jn = 0; jn < 8; jn++) {
        int ix = r * 33 + qd * 8 + jn;
        float w = __expf(ew[ix] - M);
        ew[ix] = w;
        ssum += w;
    }
    reds[qd][r] = ssum;
    __syncthreads();
    if (qd == 0) {
        d_pm[(s * HH + h) * NN + i0 + r] = M;
        d_ps[(s * HH + h) * NN + i0 + r] = reds[0][r] + reds[1][r] + reds[2][r] + reds[3][r];
    }

    // ---- phase 3: aggregation (packed f32x2) ----
    int ib2 = tid >> 4;
    int f   = (tid & 15) * 4;
    ull acc0[4] = {0,0,0,0}, acc1[4] = {0,0,0,0};
    #pragma unroll
    for (int j2 = 0; j2 < 32; j2++) {
        ull g01 = *(const ull*)&grj[j2 * 64 + f];
        ull g23 = *(const ull*)&grj[j2 * 64 + f + 2];
        #pragma unroll
        for (int q = 0; q < 4; q++) {
            float w = ew[(ib2 + q * 8) * 33 + j2];
            ull ww = f2pack(w, w);
            acc0[q] = f2fma(ww, g01, acc0[q]);
            acc1[q] = f2fma(ww, g23, acc1[q]);
        }
    }
    #pragma unroll
    for (int q = 0; q < 4; q++) {
        int i = i0 + ib2 + q * 8;
        *(float4*)&d_part[(s * NN + i) * DD + h * FF + f] =
            make_float4(f2lo(acc0[q]), f2hi(acc0[q]), f2lo(acc1[q]), f2hi(acc1[q]));
    }
}

// ============================================================
// Kernel 3: finalize. Combine per-split partials with softmax normalization,
// residual + optional ELU. If write_x1: also emit bf16 hi/lo of x1.
// Grid (12, 8), 256 threads.
// ============================================================
__global__ __launch_bounds__(256) void finalize_kernel(
    const float* __restrict__ xin_ext, int use_x1_in,
    float* __restrict__ out_ext, int write_x1, int do_elu)
{
    const float* xin  = use_x1_in ? d_x1 : xin_ext;
    float*       outp = write_x1  ? d_x1 : out_ext;
    __shared__ float coef[32][SPL + 1];

    int tid = threadIdx.x;
    int i0 = blockIdx.x * 32;
    int h  = blockIdx.y;

    if (tid < 32) {
        int r = tid;
        float m[SPL], c[SPL];
        float M = -1e38f;
        #pragma unroll
        for (int s2 = 0; s2 < SPL; s2++) {
            m[s2] = d_pm[(s2 * HH + h) * NN + i0 + r];
            M = fmaxf(M, m[s2]);
        }
        float D = 0.f;
        #pragma unroll
        for (int s2 = 0; s2 < SPL; s2++) {
            c[s2] = __expf(m[s2] - M);
            D += d_ps[(s2 * HH + h) * NN + i0 + r] * c[s2];
        }
        float invD = 1.f / D;
        #pragma unroll
        for (int s2 = 0; s2 < SPL; s2++) coef[r][s2] = c[s2] * invD;
    }
    __syncthreads();

    int il = tid >> 3;
    int f8 = (tid & 7) * 8;
    int i  = i0 + il;
    int base = i * DD + h * FF + f8;

    float4 A = {0,0,0,0}, B = {0,0,0,0};
    #pragma unroll
    for (int s2 = 0; s2 < SPL; s2++) {
        float cc = coef[il][s2];
        const float* pp = &d_part[(s2 * NN + i) * DD + h * FF + f8];
        float4 p = *(const float4*)pp;
        float4 q = *(const float4*)(pp + 4);
        A.x = fmaf(cc, p.x, A.x); A.y = fmaf(cc, p.y, A.y);
        A.z = fmaf(cc, p.z, A.z); A.w = fmaf(cc, p.w, A.w);
        B.x = fmaf(cc, q.x, B.x); B.y = fmaf(cc, q.y, B.y);
        B.z = fmaf(cc, q.z, B.z); B.w = fmaf(cc, q.w, B.w);
    }
    if (do_elu) {
        A.x = A.x > 0.f ? A.x : expm1f(A.x);
        A.y = A.y > 0.f ? A.y : expm1f(A.y);
        A.z = A.z > 0.f ? A.z : expm1f(A.z);
        A.w = A.w > 0.f ? A.w : expm1f(A.w);
        B.x = B.x > 0.f ? B.x : expm1f(B.x);
        B.y = B.y > 0.f ? B.y : expm1f(B.y);
        B.z = B.z > 0.f ? B.z : expm1f(B.z);
        B.w = B.w > 0.f ? B.w : expm1f(B.w);
    }
    float4 xa = *(const float4*)&xin[base];
    float4 xb = *(const float4*)&xin[base + 4];
    float4 oA = make_float4(xa.x + A.x, xa.y + A.y, xa.z + A.z, xa.w + A.w);
    float4 oB = make_float4(xb.x + B.x, xb.y + B.y, xb.z + B.z, xb.w + B.w);
    *(float4*)&outp[base]     = oA;
    *(float4*)&outp[base + 4] = oB;

    if (write_x1) {
        __nv_bfloat16* xh = d_xbh + NN * DD;
        __nv_bfloat16* xl = d_xbl + NN * DD;
        float v[8] = {oA.x, oA.y, oA.z, oA.w, oB.x, oB.y, oB.z, oB.w};
        #pragma unroll
        for (int p = 0; p < 4; p++) {
            __nv_bfloat162 hh, ll;
            hh.x = __float2bfloat16(v[2*p]);
            hh.y = __float2bfloat16(v[2*p + 1]);
            ll.x = __float2bfloat16(v[2*p]     - __bfloat162float(hh.x));
            ll.y = __float2bfloat16(v[2*p + 1] - __bfloat162float(hh.y));
            *(__nv_bfloat162*)&xh[base + 2*p] = hh;
            *(__nv_bfloat162*)&xl[base + 2*p] = ll;
        }
    }
}

// ============================================================
extern "C" void kernel_launch(void* const* d_in, const int* in_sizes, int n_in,
                              void* d_out, int out_size)
{
    const float* x   = (const float*)d_in[0];
    const int*   adj = (const int*)  d_in[1];
    const float* Wl0 = (const float*)d_in[2];
    const float* Wr0 = (const float*)d_in[3];
    const float* a0  = (const float*)d_in[4];
    const float* Wl1 = (const float*)d_in[5];
    const float* Wr1 = (const float*)d_in[6];
    const float* a1  = (const float*)d_in[7];
    float* out = (float*)d_out;

    dim3 gc(256, 5);            // convert: W x4 + x
    dim3 gg(16, 12);            // gemm: 192 blocks x 256 thr
    dim3 gat(12, 8, SPL);       // fused attention: 1152 blocks
    dim3 gf(12, 8);             // finalize: 96 blocks

    convert_kernel<<<gc, 256>>>(x, Wl0, Wr0, Wl1, Wr1);

    // ---- layer 0 ----
    gemm_kernel<<<gg, 256>>>(0, a0);
    attn_kernel<<<gat, 128>>>(a0, adj);
    finalize_kernel<<<gf, 256>>>(x, 0, nullptr, /*write_x1=*/1, /*elu=*/1);

    // ---- layer 1 ----
    gemm_kernel<<<gg, 256>>>(1, a1);
    attn_kernel<<<gat, 128>>>(a1, adj);
    finalize_kernel<<<gf, 256>>>(nullptr, 1, out, /*write_x1=*/0, /*elu=*/0);
}

// round 14
// speedup vs baseline: 2.5045x; 1.0339x over previous
#include <cuda_runtime.h>
#include <cuda_bf16.h>
#include <math.h>
#include <stdint.h>

#define NN 384
#define DD 512
#define HH 8
#define FF 64
#define SPL 6

typedef unsigned long long ull;

// ---- scratch (no allocations allowed) ----
__device__ float d_gl[NN * DD];
__device__ float d_gr[NN * DD];
__device__ float d_x1[NN * DD];
__device__ float d_rvec[HH * NN];
__device__ float d_lvec[HH * NN];
__device__ float d_part[SPL * NN * DD];
__device__ float d_pm[SPL * HH * NN];
__device__ float d_ps[SPL * HH * NN];
// bf16 hi/lo operand storage
__device__ __nv_bfloat16 d_wbh[4 * DD * DD];
__device__ __nv_bfloat16 d_wbl[4 * DD * DD];
__device__ __nv_bfloat16 d_xbh[2 * NN * DD];
__device__ __nv_bfloat16 d_xbl[2 * NN * DD];

// ---- packed f32x2 helpers ----
__device__ __forceinline__ ull f2add(ull a, ull b) {
    ull r; asm("add.rn.f32x2 %0, %1, %2;" : "=l"(r) : "l"(a), "l"(b)); return r;
}
__device__ __forceinline__ ull f2fma(ull a, ull b, ull c) {
    ull r; asm("fma.rn.f32x2 %0, %1, %2, %3;" : "=l"(r) : "l"(a), "l"(b), "l"(c)); return r;
}
__device__ __forceinline__ ull f2pack(float lo, float hi) {
    ull r; asm("mov.b64 %0, {%1, %2};" : "=l"(r) : "r"(__float_as_uint(lo)), "r"(__float_as_uint(hi)));
    return r;
}
__device__ __forceinline__ float f2lo(ull v) { return __uint_as_float((unsigned)(v & 0xFFFFFFFFu)); }
__device__ __forceinline__ float f2hi(ull v) { return __uint_as_float((unsigned)(v >> 32)); }

__device__ __forceinline__ uint32_t smem_u32(const void* p) {
    uint32_t a;
    asm("{ .reg .u64 t; cvta.to.shared.u64 t, %1; cvt.u32.u64 %0, t; }" : "=r"(a) : "l"(p));
    return a;
}
__device__ __forceinline__ void ldsm4(uint32_t r[4], uint32_t addr) {
    asm volatile("ldmatrix.sync.aligned.m8n8.x4.shared.b16 {%0,%1,%2,%3}, [%4];"
                 : "=r"(r[0]), "=r"(r[1]), "=r"(r[2]), "=r"(r[3]) : "r"(addr));
}
__device__ __forceinline__ void ldsm4t(uint32_t r[4], uint32_t addr) {
    asm volatile("ldmatrix.sync.aligned.m8n8.x4.trans.shared.b16 {%0,%1,%2,%3}, [%4];"
                 : "=r"(r[0]), "=r"(r[1]), "=r"(r[2]), "=r"(r[3]) : "r"(addr));
}
__device__ __forceinline__ void mma16816(float c[4], const uint32_t a[4],
                                         uint32_t b0, uint32_t b1) {
    asm volatile(
        "mma.sync.aligned.m16n8k16.row.col.f32.bf16.bf16.f32 "
        "{%0,%1,%2,%3}, {%4,%5,%6,%7}, {%8,%9}, {%0,%1,%2,%3};\n"
        : "+f"(c[0]), "+f"(c[1]), "+f"(c[2]), "+f"(c[3])
        : "r"(a[0]), "r"(a[1]), "r"(a[2]), "r"(a[3]), "r"(b0), "r"(b1));
}

// ============================================================
// Kernel 0: one-time fp32 -> bf16 hi/lo conversion of W (x4) and x.
// ============================================================
__global__ __launch_bounds__(256) void convert_kernel(
    const float* __restrict__ x,
    const float* __restrict__ Wl0, const float* __restrict__ Wr0,
    const float* __restrict__ Wl1, const float* __restrict__ Wr1)
{
    int by = blockIdx.y;
    const float* src;
    __nv_bfloat16 *dh, *dl;
    int limit;
    if (by < 4) {
        src = (by == 0) ? Wl0 : (by == 1) ? Wr0 : (by == 2) ? Wl1 : Wr1;
        dh = d_wbh + by * DD * DD; dl = d_wbl + by * DD * DD; limit = DD * DD;
    } else {
        src = x; dh = d_xbh; dl = d_xbl; limit = NN * DD;
    }
    int e = (blockIdx.x * 256 + threadIdx.x) * 4;
    if (e >= limit) return;
    float4 v = *(const float4*)&src[e];
    __nv_bfloat162 h0, h1, l0, l1;
    h0.x = __float2bfloat16(v.x); h0.y = __float2bfloat16(v.y);
    h1.x = __float2bfloat16(v.z); h1.y = __float2bfloat16(v.w);
    l0.x = __float2bfloat16(v.x - __bfloat162float(h0.x));
    l0.y = __float2bfloat16(v.y - __bfloat162float(h0.y));
    l1.x = __float2bfloat16(v.z - __bfloat162float(h1.x));
    l1.y = __float2bfloat16(v.w - __bfloat162float(h1.y));
    *(__nv_bfloat162*)&dh[e]     = h0;
    *(__nv_bfloat162*)&dh[e + 2] = h1;
    *(__nv_bfloat162*)&dl[e]     = l0;
    *(__nv_bfloat162*)&dl[e + 2] = l1;
}

// ============================================================
// Kernel 1: bf16x3 tensor-core GEMM (unchanged from R13).
// ============================================================
__global__ __launch_bounds__(256) void gemm_kernel(int layer, const float* __restrict__ a_vec)
{
    __shared__ __align__(16) __nv_bfloat16 Ah[32][72], Al[32][72];
    __shared__ __align__(16) __nv_bfloat16 Bh[64][72], Bl[64][72];
    __shared__ float red[4][33];

    int tid = threadIdx.x;
    int bx  = blockIdx.x;
    int i0  = blockIdx.y * 32;
    int isL = (bx < 8);
    int c0  = (bx & 7) * 64;
    int widx = layer * 2 + (isL ? 0 : 1);
    const __nv_bfloat16* A_h = d_xbh + layer * NN * DD;
    const __nv_bfloat16* A_l = d_xbl + layer * NN * DD;
    const __nv_bfloat16* W_h = d_wbh + widx * DD * DD;
    const __nv_bfloat16* W_l = d_wbl + widx * DD * DD;
    float* outp = isL ? d_gl : d_gr;

    int warp = tid >> 5, lane = tid & 31;
    int wm = warp >> 2, wn = warp & 3;

    int ar = tid >> 3, ac = (tid & 7) * 8;
    int br = tid >> 2, bc = (tid & 3) * 16;

    uint32_t aadr_h = smem_u32(&Ah[wm * 16 + (lane & 15)][(lane >> 4) * 8]);
    uint32_t aadr_l = smem_u32(&Al[wm * 16 + (lane & 15)][(lane >> 4) * 8]);
    int bkrow = (lane & 7) + ((lane >> 3) & 1) * 8;
    uint32_t badr_h = smem_u32(&Bh[bkrow][wn * 16 + (lane >> 4) * 8]);
    uint32_t badr_l = smem_u32(&Bl[bkrow][wn * 16 + (lane >> 4) * 8]);

    float c0f[4] = {0,0,0,0};
    float c1f[4] = {0,0,0,0};

    uint4 pah, pal, pbh0, pbh1, pbl0, pbl1;
    pah  = *(const uint4*)&A_h[(i0 + ar) * DD + ac];
    pal  = *(const uint4*)&A_l[(i0 + ar) * DD + ac];
    pbh0 = *(const uint4*)&W_h[br * DD + c0 + bc];
    pbh1 = *(const uint4*)&W_h[br * DD + c0 + bc + 8];
    pbl0 = *(const uint4*)&W_l[br * DD + c0 + bc];
    pbl1 = *(const uint4*)&W_l[br * DD + c0 + bc + 8];

    for (int k0 = 0; k0 < DD; k0 += 64) {
        *(uint4*)&Ah[ar][ac]      = pah;
        *(uint4*)&Al[ar][ac]      = pal;
        *(uint4*)&Bh[br][bc]      = pbh0;
        *(uint4*)&Bh[br][bc + 8]  = pbh1;
        *(uint4*)&Bl[br][bc]      = pbl0;
        *(uint4*)&Bl[br][bc + 8]  = pbl1;
        __syncthreads();

        int kn = k0 + 64;
        if (kn < DD) {
            pah  = *(const uint4*)&A_h[(i0 + ar) * DD + kn + ac];
            pal  = *(const uint4*)&A_l[(i0 + ar) * DD + kn + ac];
            pbh0 = *(const uint4*)&W_h[(kn + br) * DD + c0 + bc];
            pbh1 = *(const uint4*)&W_h[(kn + br) * DD + c0 + bc + 8];
            pbl0 = *(const uint4*)&W_l[(kn + br) * DD + c0 + bc];
            pbl1 = *(const uint4*)&W_l[(kn + br) * DD + c0 + bc + 8];
        }

        #pragma unroll
        for (int kc = 0; kc < 4; kc++) {
            uint32_t ah[4], al[4], bh[4], bl[4];
            ldsm4 (ah, aadr_h + kc * 32);
            ldsm4 (al, aadr_l + kc * 32);
            ldsm4t(bh, badr_h + kc * 16 * 144);
            ldsm4t(bl, badr_l + kc * 16 * 144);
            mma16816(c0f, ah, bh[0], bh[1]);
            mma16816(c0f, al, bh[0], bh[1]);
            mma16816(c0f, ah, bl[0], bl[1]);
            mma16816(c1f, ah, bh[2], bh[3]);
            mma16816(c1f, al, bh[2], bh[3]);
            mma16816(c1f, ah, bl[2], bl[3]);
        }
        __syncthreads();
    }

    int r0 = i0 + wm * 16 + (lane >> 2);
    int r1 = r0 + 8;
    int cb = c0 + wn * 16 + 2 * (lane & 3);
    *(float2*)&outp[r0 * DD + cb]     = make_float2(c0f[0], c0f[1]);
    *(float2*)&outp[r0 * DD + cb + 8] = make_float2(c1f[0], c1f[1]);
    *(float2*)&outp[r1 * DD + cb]     = make_float2(c0f[2], c0f[3]);
    *(float2*)&outp[r1 * DD + cb + 8] = make_float2(c1f[2], c1f[3]);

    int f0 = wn * 16 + 2 * (lane & 3);
    float af0 = a_vec[f0], af1 = a_vec[f0 + 1];
    float af8 = a_vec[f0 + 8], af9 = a_vec[f0 + 9];
    float p0 = af0 * c0f[0] + af1 * c0f[1] + af8 * c1f[0] + af9 * c1f[1];
    float p1 = af0 * c0f[2] + af1 * c0f[3] + af8 * c1f[2] + af9 * c1f[3];
    p0 += __shfl_xor_sync(0xffffffffu, p0, 1);
    p0 += __shfl_xor_sync(0xffffffffu, p0, 2);
    p1 += __shfl_xor_sync(0xffffffffu, p1, 1);
    p1 += __shfl_xor_sync(0xffffffffu, p1, 2);
    if ((lane & 3) == 0) {
        red[wn][wm * 16 + (lane >> 2)]     = p0;
        red[wn][wm * 16 + 8 + (lane >> 2)] = p1;
    }
    __syncthreads();
    if (tid < 32) {
        int h = bx & 7;
        float* dst = isL ? d_lvec : d_rvec;
        dst[h * NN + i0 + tid] = red[0][tid] + red[1][tid] + red[2][tid] + red[3][tid];
    }
}

// ============================================================
// Kernel 2: FUSED attention, 64-j split per block (2 sub-tiles of 32).
// Block = (32 i-rows, head h, split s of 64 j). Grid (12, 8, 6) = 576 blocks.
// One shared buf is reused: glj in phase 1, grj in phase 3.
// ============================================================
__global__ __launch_bounds__(128) void attn_kernel(
    const float* __restrict__ a_vec, const int* __restrict__ adj)
{
    __shared__ __align__(16) float gri[32 * 64];
    __shared__ __align__(16) float buf[32 * 66];
    __shared__ __align__(16) float ew[32 * 65];   // 32 i x 64 j (+pad)
    __shared__ __align__(16) float as[64];
    __shared__ float rvs[32], lvs[64];
    __shared__ float redm[4][32], reds[4][32];

    int tid = threadIdx.x;
    int i0 = blockIdx.x * 32;
    int h  = blockIdx.y;
    int s  = blockIdx.z;
    int jb = s * 64;

    if (tid < 64) {
        as[tid]  = a_vec[tid];
        lvs[tid] = d_lvec[h * NN + jb + tid];
    } else if (tid < 96) {
        rvs[tid - 64] = d_rvec[h * NN + i0 + (tid - 64)];
    }

    #pragma unroll
    for (int p = 0; p < 4; p++) {
        int idx = tid + p * 128;
        int r = idx >> 4, f4 = (idx & 15) * 4;
        *(float4*)&gri[r * 64 + f4] = *(const float4*)&d_gr[(i0 + r) * DD + h * FF + f4];
    }

    int jj = tid & 31;
    int ib = tid >> 5;
    int mk[2][8];
    #pragma unroll
    for (int jt = 0; jt < 2; jt++)
        #pragma unroll
        for (int q = 0; q < 8; q++) {
            int i = i0 + ib + q * 4;
            int j = jb + jt * 32 + jj;
            mk[jt][q] = (adj[i * NN + j] != 0) || (i == j);
        }

    // ---- phase 1: logits, two 32-j sub-tiles through shared buf ----
    #pragma unroll 1
    for (int jt = 0; jt < 2; jt++) {
        __syncthreads();   // buf free (first iter: also covers gri/as/etc fills)
        #pragma unroll
        for (int p = 0; p < 4; p++) {
            int idx = tid + p * 128;
            int r = idx >> 4, f4 = (idx & 15) * 4;
            float4 w = *(const float4*)&d_gl[(jb + jt * 32 + r) * DD + h * FF + f4];
            *(float2*)&buf[r * 66 + f4]     = make_float2(w.x, w.y);
            *(float2*)&buf[r * 66 + f4 + 2] = make_float2(w.z, w.w);
        }
        __syncthreads();

        ull accp[8] = {0,0,0,0,0,0,0,0};
        #pragma unroll 8
        for (int f = 0; f < 64; f += 2) {
            ull gl2 = *(const ull*)&buf[jj * 66 + f];
            ull a2  = *(const ull*)&as[f];
            #pragma unroll
            for (int q = 0; q < 8; q++) {
                ull v = f2add(*(const ull*)&gri[(ib + q * 4) * 64 + f], gl2);
                v &= 0x7FFFFFFF7FFFFFFFULL;
                accp[q] = f2fma(a2, v, accp[q]);
            }
        }
        float lvj = lvs[jt * 32 + jj];
        #pragma unroll
        for (int q = 0; q < 8; q++) {
            int il = ib + q * 4;
            float sum = f2lo(accp[q]) + f2hi(accp[q]);
            float e = 0.6f * (rvs[il] + lvj) + 0.4f * sum;
            ew[il * 65 + jt * 32 + jj] = mk[jt][q] ? e : -1e30f;
        }
    }
    __syncthreads();

    // ---- phase 2: per-row stats over 64 j + exp in place ----
    int r  = tid & 31;
    int qd = tid >> 5;
    float pm = -1e38f;
    #pragma unroll
    for (int jn = 0; jn < 16; jn++) pm = fmaxf(pm, ew[r * 65 + qd * 16 + jn]);
    redm[qd][r] = pm;
    __syncthreads();
    float M = fmaxf(fmaxf(redm[0][r], redm[1][r]), fmaxf(redm[2][r], redm[3][r]));
    float ssum = 0.f;
    #pragma unroll
    for (int jn = 0; jn < 16; jn++) {
        int ix = r * 65 + qd * 16 + jn;
        float w = __expf(ew[ix] - M);
        ew[ix] = w;
        ssum += w;
    }
    reds[qd][r] = ssum;
    __syncthreads();
    if (qd == 0) {
        d_pm[(s * HH + h) * NN + i0 + r] = M;
        d_ps[(s * HH + h) * NN + i0 + r] = reds[0][r] + reds[1][r] + reds[2][r] + reds[3][r];
    }

    // ---- phase 3: aggregation over 64 j, grj through shared buf ----
    int ib2 = tid >> 4;
    int f   = (tid & 15) * 4;
    ull acc0[4] = {0,0,0,0}, acc1[4] = {0,0,0,0};
    #pragma unroll 1
    for (int jt = 0; jt < 2; jt++) {
        #pragma unroll
        for (int p = 0; p < 4; p++) {
            int idx = tid + p * 128;
            int rr = idx >> 4, f4 = (idx & 15) * 4;
            *(float4*)&buf[rr * 64 + f4] =
                *(const float4*)&d_gr[(jb + jt * 32 + rr) * DD + h * FF + f4];
        }
        __syncthreads();
        #pragma unroll
        for (int j2 = 0; j2 < 32; j2++) {
            ull g01 = *(const ull*)&buf[j2 * 64 + f];
            ull g23 = *(const ull*)&buf[j2 * 64 + f + 2];
            #pragma unroll
            for (int q = 0; q < 4; q++) {
                float w = ew[(ib2 + q * 8) * 65 + jt * 32 + j2];
                ull ww = f2pack(w, w);
                acc0[q] = f2fma(ww, g01, acc0[q]);
                acc1[q] = f2fma(ww, g23, acc1[q]);
            }
        }
        __syncthreads();
    }
    #pragma unroll
    for (int q = 0; q < 4; q++) {
        int i = i0 + ib2 + q * 8;
        *(float4*)&d_part[(s * NN + i) * DD + h * FF + f] =
            make_float4(f2lo(acc0[q]), f2hi(acc0[q]), f2lo(acc1[q]), f2hi(acc1[q]));
    }
}

// ============================================================
// Kernel 3: finalize. Grid (48, 8) = 384 blocks x 128 thr; 8 i-rows/block,
// one float4/thread over SPL=6 partial splits. Residual + optional ELU.
// If write_x1: also emit bf16 hi/lo of x1.
// ============================================================
__global__ __launch_bounds__(128) void finalize_kernel(
    const float* __restrict__ xin_ext, int use_x1_in,
    float* __restrict__ out_ext, int write_x1, int do_elu)
{
    const float* xin  = use_x1_in ? d_x1 : xin_ext;
    float*       outp = write_x1  ? d_x1 : out_ext;
    __shared__ float coef[8][SPL + 2];

    int tid = threadIdx.x;
    int i0 = blockIdx.x * 8;
    int h  = blockIdx.y;

    if (tid < 8) {
        int r = tid;
        float m[SPL], c[SPL];
        float M = -1e38f;
        #pragma unroll
        for (int s2 = 0; s2 < SPL; s2++) {
            m[s2] = d_pm[(s2 * HH + h) * NN + i0 + r];
            M = fmaxf(M, m[s2]);
        }
        float D = 0.f;
        #pragma unroll
        for (int s2 = 0; s2 < SPL; s2++) {
            c[s2] = __expf(m[s2] - M);
            D += d_ps[(s2 * HH + h) * NN + i0 + r] * c[s2];
        }
        float invD = 1.f / D;
        #pragma unroll
        for (int s2 = 0; s2 < SPL; s2++) coef[r][s2] = c[s2] * invD;
    }
    __syncthreads();

    int il = tid >> 4;
    int f4 = (tid & 15) * 4;
    int i  = i0 + il;
    int base = i * DD + h * FF + f4;

    float4 A = {0,0,0,0};
    #pragma unroll
    for (int s2 = 0; s2 < SPL; s2++) {
        float cc = coef[il][s2];
        float4 p = *(const float4*)&d_part[(s2 * NN + i) * DD + h * FF + f4];
        A.x = fmaf(cc, p.x, A.x); A.y = fmaf(cc, p.y, A.y);
        A.z = fmaf(cc, p.z, A.z); A.w = fmaf(cc, p.w, A.w);
    }
    if (do_elu) {
        A.x = A.x > 0.f ? A.x : expm1f(A.x);
        A.y = A.y > 0.f ? A.y : expm1f(A.y);
        A.z = A.z > 0.f ? A.z : expm1f(A.z);
        A.w = A.w > 0.f ? A.w : expm1f(A.w);
    }
    float4 xa = *(const float4*)&xin[base];
    float4 oA = make_float4(xa.x + A.x, xa.y + A.y, xa.z + A.z, xa.w + A.w);
    *(float4*)&outp[base] = oA;

    if (write_x1) {
        __nv_bfloat16* xh = d_xbh + NN * DD;
        __nv_bfloat16* xl = d_xbl + NN * DD;
        __nv_bfloat162 h0, h1, l0, l1;
        h0.x = __float2bfloat16(oA.x); h0.y = __float2bfloat16(oA.y);
        h1.x = __float2bfloat16(oA.z); h1.y = __float2bfloat16(oA.w);
        l0.x = __float2bfloat16(oA.x - __bfloat162float(h0.x));
        l0.y = __float2bfloat16(oA.y - __bfloat162float(h0.y));
        l1.x = __float2bfloat16(oA.z - __bfloat162float(h1.x));
        l1.y = __float2bfloat16(oA.w - __bfloat162float(h1.y));
        *(__nv_bfloat162*)&xh[base]     = h0;
        *(__nv_bfloat162*)&xh[base + 2] = h1;
        *(__nv_bfloat162*)&xl[base]     = l0;
        *(__nv_bfloat162*)&xl[base + 2] = l1;
    }
}

// ============================================================
extern "C" void kernel_launch(void* const* d_in, const int* in_sizes, int n_in,
                              void* d_out, int out_size)
{
    const float* x   = (const float*)d_in[0];
    const int*   adj = (const int*)  d_in[1];
    const float* Wl0 = (const float*)d_in[2];
    const float* Wr0 = (const float*)d_in[3];
    const float* a0  = (const float*)d_in[4];
    const float* Wl1 = (const float*)d_in[5];
    const float* Wr1 = (const float*)d_in[6];
    const float* a1  = (const float*)d_in[7];
    float* out = (float*)d_out;

    dim3 gc(256, 5);            // convert
    dim3 gg(16, 12);            // gemm: 192 blocks x 256 thr
    dim3 gat(12, 8, SPL);       // fused attention: 576 blocks
    dim3 gf(48, 8);             // finalize: 384 blocks x 128 thr

    convert_kernel<<<gc, 256>>>(x, Wl0, Wr0, Wl1, Wr1);

    // ---- layer 0 ----
    gemm_kernel<<<gg, 256>>>(0, a0);
    attn_kernel<<<gat, 128>>>(a0, adj);
    finalize_kernel<<<gf, 128>>>(x, 0, nullptr, /*write_x1=*/1, /*elu=*/1);

    // ---- layer 1 ----
    gemm_kernel<<<gg, 256>>>(1, a1);
    attn_kernel<<<gat, 128>>>(a1, adj);
    finalize_kernel<<<gf, 128>>>(nullptr, 1, out, /*write_x1=*/0, /*elu=*/0);
}